// round 7
// baseline (speedup 1.0000x reference)
#include <cuda_runtime.h>
#include <math.h>
#include <stdint.h>

// ---------------------------------------------------------------------------
// Problem constants
// ---------------------------------------------------------------------------
#define EPSLN 1e-5f
#define DT    0.01f
#define CDIM  256
#define BDIM  8
#define NTOK  256
#define HEADS 8
#define HD    32
#define ROWS  (BDIM * NTOK)   // 2048

// ODE tiling
#define MROW 16          // rows per CTA
#define MP   20          // padded row-stride (floats) in transposed smem buffers
#define MPB  (MP * 4)    // 80 bytes
#define KB   32          // k-block size for weight staging
#define WBYTES (KB * CDIM * 4)   // 32 KB per weight block

// smem byte offsets for ODE kernel
#define OFF_YS   0
#define OFF_K1   20480
#define OFF_K2   40960
#define OFF_K3   61440
#define OFF_ARGS 81920
#define OFF_H1   102400
#define OFF_W0   122880
#define OFF_W1   155648
#define OFF_PS   188416       // 16 KB k-split partial sums
#define OFF_RED  204800
#define ODE_SMEM 205312

typedef unsigned long long U64;

// ---------------------------------------------------------------------------
// Scratch (device globals: no allocation allowed)
// ---------------------------------------------------------------------------
__device__ float g_qbuf[3 * BDIM * HEADS * NTOK * HD]; // [3][B][H][N][hd]
__device__ float g_attnout[ROWS * CDIM];               // attention concat [B*N][C]
__device__ float g_x1[ROWS * CDIM];                    // x1 = LN(x + attn)
__device__ float g_ode[ROWS * CDIM];                   // ODE output at lead time

// ---------------------------------------------------------------------------
// packed f32x2 helpers (Blackwell FFMA2 path)
// ---------------------------------------------------------------------------
__device__ __forceinline__ U64 pack2(float lo, float hi) {
    U64 r; asm("mov.b64 %0, {%1, %2};" : "=l"(r) : "f"(lo), "f"(hi)); return r;
}
__device__ __forceinline__ void unpack2(U64 v, float& lo, float& hi) {
    asm("mov.b64 {%0, %1}, %2;" : "=f"(lo), "=f"(hi) : "l"(v));
}
__device__ __forceinline__ U64 fma2(U64 a, U64 b, U64 c) {
    U64 d; asm("fma.rn.f32x2 %0, %1, %2, %3;" : "=l"(d) : "l"(a), "l"(b), "l"(c)); return d;
}
__device__ __forceinline__ U64 add2(U64 a, U64 b) {
    U64 d; asm("add.rn.f32x2 %0, %1, %2;" : "=l"(d) : "l"(a), "l"(b)); return d;
}
__device__ __forceinline__ U64 mul2(U64 a, U64 b) {
    U64 d; asm("mul.rn.f32x2 %0, %1, %2;" : "=l"(d) : "l"(a), "l"(b)); return d;
}
__device__ __forceinline__ void lds2x64(uint32_t addr, U64& a, U64& b) {
    asm volatile("ld.shared.v2.b64 {%0, %1}, [%2];" : "=l"(a), "=l"(b) : "r"(addr));
}
__device__ __forceinline__ void lds2f(uint32_t addr, float& a, float& b) {
    asm volatile("ld.shared.v2.f32 {%0, %1}, [%2];" : "=f"(a), "=f"(b) : "r"(addr));
}
__device__ __forceinline__ void lds4f(uint32_t addr, float& x, float& y, float& z, float& w) {
    asm volatile("ld.shared.v4.f32 {%0, %1, %2, %3}, [%4];"
                 : "=f"(x), "=f"(y), "=f"(z), "=f"(w) : "r"(addr));
}
__device__ __forceinline__ void sts2x64(uint32_t addr, U64 a, U64 b) {
    asm volatile("st.shared.v2.b64 [%0], {%1, %2};" :: "r"(addr), "l"(a), "l"(b));
}
__device__ __forceinline__ void sts4f(uint32_t addr, float x, float y, float z, float w) {
    asm volatile("st.shared.v4.f32 [%0], {%1, %2, %3, %4};"
                 :: "r"(addr), "f"(x), "f"(y), "f"(z), "f"(w));
}
__device__ __forceinline__ void cp_async16(uint32_t sdst, const void* gsrc) {
    asm volatile("cp.async.cg.shared.global [%0], [%1], 16;" :: "r"(sdst), "l"(gsrc));
}
__device__ __forceinline__ void cp_commit() { asm volatile("cp.async.commit_group;"); }
__device__ __forceinline__ void cp_wait1() { asm volatile("cp.async.wait_group 1;" ::: "memory"); }
__device__ __forceinline__ void cp_wait_all() { asm volatile("cp.async.wait_group 0;" ::: "memory"); }

// ---------------------------------------------------------------------------
// K1: qkv = x @ wqkv + bqkv, scattered into [3][B][H][N][hd]
// ---------------------------------------------------------------------------
__global__ void qkv_kernel(const float* __restrict__ x,
                           const float* __restrict__ wqkv,
                           const float* __restrict__ bqkv) {
    __shared__ __align__(16) float As[CDIM * 36];
    int tid = threadIdx.x, cg = tid & 31, rg = tid >> 5;
    int r0 = blockIdx.x * 32;
    int cb = blockIdx.y;

    for (int idx = tid; idx < 32 * CDIM; idx += 256) {
        int c = idx & 255, m = idx >> 8;
        As[c * 36 + m] = x[(r0 + m) * CDIM + c];
    }
    __syncthreads();

    float acc[4][8];
#pragma unroll
    for (int j = 0; j < 8; j++) {
        float bv = bqkv[cb * 256 + cg + 32 * j];
#pragma unroll
        for (int mm = 0; mm < 4; mm++) acc[mm][j] = bv;
    }
    int m0 = rg * 4;
    const float* wp = wqkv + cb * 256 + cg;
#pragma unroll 4
    for (int k = 0; k < CDIM; k++) {
        float4 av = *(const float4*)(As + k * 36 + m0);
#pragma unroll
        for (int j = 0; j < 8; j++) {
            float w = wp[k * 768 + 32 * j];
            acc[0][j] = fmaf(av.x, w, acc[0][j]);
            acc[1][j] = fmaf(av.y, w, acc[1][j]);
            acc[2][j] = fmaf(av.z, w, acc[2][j]);
            acc[3][j] = fmaf(av.w, w, acc[3][j]);
        }
    }
#pragma unroll
    for (int mm = 0; mm < 4; mm++) {
        int r = r0 + m0 + mm;
        int b = r >> 8, n = r & 255;
#pragma unroll
        for (int j = 0; j < 8; j++) {
            int cl = cg + 32 * j;
            int h = cl >> 5, d = cl & 31;
            g_qbuf[(((cb * BDIM + b) * HEADS + h) * NTOK + n) * HD + d] = acc[mm][j];
        }
    }
}

// ---------------------------------------------------------------------------
// K2: per-(b,h) softmax attention
// ---------------------------------------------------------------------------
#define ATTN_SMEM ((3 * 256 * 33 + 8 * 256) * 4)

__global__ void attn_kernel() {
    extern __shared__ float sm[];
    float* qs = sm;
    float* ks = qs + 256 * 33;
    float* vs = ks + 256 * 33;
    float* prob = vs + 256 * 33;

    int tid = threadIdx.x, lane = tid & 31, w = tid >> 5;
    int bh = blockIdx.x, b = bh >> 3, h = bh & 7;
    const float scale = 0.17677669529663687f;

    const float* qg = g_qbuf + ((0 * BDIM + b) * HEADS + h) * NTOK * HD;
    const float* kg = g_qbuf + ((1 * BDIM + b) * HEADS + h) * NTOK * HD;
    const float* vg = g_qbuf + ((2 * BDIM + b) * HEADS + h) * NTOK * HD;
    for (int idx = tid; idx < NTOK * HD; idx += 256) {
        int n = idx >> 5, d = idx & 31;
        qs[n * 33 + d] = qg[idx] * scale;
        ks[n * 33 + d] = kg[idx];
        vs[n * 33 + d] = vg[idx];
    }
    __syncthreads();

    for (int n = w; n < NTOK; n += 8) {
        float s[8];
#pragma unroll
        for (int u = 0; u < 8; u++) {
            int j = lane + 32 * u;
            float a = 0.f;
#pragma unroll 8
            for (int d = 0; d < HD; d++) a = fmaf(qs[n * 33 + d], ks[j * 33 + d], a);
            s[u] = a;
        }
        float mx = s[0];
#pragma unroll
        for (int u = 1; u < 8; u++) mx = fmaxf(mx, s[u]);
#pragma unroll
        for (int o = 16; o > 0; o >>= 1) mx = fmaxf(mx, __shfl_xor_sync(0xffffffffu, mx, o));
        float sum = 0.f;
#pragma unroll
        for (int u = 0; u < 8; u++) { s[u] = __expf(s[u] - mx); sum += s[u]; }
#pragma unroll
        for (int o = 16; o > 0; o >>= 1) sum += __shfl_xor_sync(0xffffffffu, sum, o);
        float inv = 1.f / sum;
#pragma unroll
        for (int u = 0; u < 8; u++) prob[w * 256 + lane + 32 * u] = s[u] * inv;
        __syncwarp();
        float acc = 0.f;
#pragma unroll 8
        for (int j = 0; j < NTOK; j++) acc = fmaf(prob[w * 256 + j], vs[j * 33 + lane], acc);
        g_attnout[(b * NTOK + n) * CDIM + h * HD + lane] = acc;
        __syncwarp();
    }
}

// ---------------------------------------------------------------------------
// K3: x1 = LN(x + attnout @ wo + bo; g1,b1)
// ---------------------------------------------------------------------------
__global__ void proj_ln_kernel(const float* __restrict__ x,
                               const float* __restrict__ wo,
                               const float* __restrict__ bo,
                               const float* __restrict__ g1,
                               const float* __restrict__ b1) {
    __shared__ __align__(16) float As[CDIM * 36];
    int tid = threadIdx.x, cg = tid & 31, rg = tid >> 5;
    int r0 = blockIdx.x * 32;
    for (int idx = tid; idx < 32 * CDIM; idx += 256) {
        int c = idx & 255, m = idx >> 8;
        As[c * 36 + m] = g_attnout[(r0 + m) * CDIM + c];
    }
    __syncthreads();

    float acc[4][8];
#pragma unroll
    for (int j = 0; j < 8; j++) {
        float bv = bo[cg + 32 * j];
#pragma unroll
        for (int mm = 0; mm < 4; mm++) acc[mm][j] = bv;
    }
    int m0 = rg * 4;
    const float* wp = wo + cg;
#pragma unroll 4
    for (int k = 0; k < CDIM; k++) {
        float4 av = *(const float4*)(As + k * 36 + m0);
#pragma unroll
        for (int j = 0; j < 8; j++) {
            float w = wp[k * CDIM + 32 * j];
            acc[0][j] = fmaf(av.x, w, acc[0][j]);
            acc[1][j] = fmaf(av.y, w, acc[1][j]);
            acc[2][j] = fmaf(av.z, w, acc[2][j]);
            acc[3][j] = fmaf(av.w, w, acc[3][j]);
        }
    }
#pragma unroll
    for (int mm = 0; mm < 4; mm++) {
        int r = r0 + m0 + mm;
#pragma unroll
        for (int j = 0; j < 8; j++) acc[mm][j] += x[r * CDIM + cg + 32 * j];
        float ls = 0.f, lq = 0.f;
#pragma unroll
        for (int j = 0; j < 8; j++) { ls += acc[mm][j]; lq += acc[mm][j] * acc[mm][j]; }
#pragma unroll
        for (int o = 16; o > 0; o >>= 1) {
            ls += __shfl_xor_sync(0xffffffffu, ls, o);
            lq += __shfl_xor_sync(0xffffffffu, lq, o);
        }
        float mean = ls * (1.f / 256.f);
        float var  = lq * (1.f / 256.f) - mean * mean;
        float rstd = rsqrtf(var + EPSLN);
#pragma unroll
        for (int j = 0; j < 8; j++) {
            int c = cg + 32 * j;
            g_x1[r * CDIM + c] = (acc[mm][j] - mean) * rstd * g1[c] + b1[c];
        }
    }
}

// ---------------------------------------------------------------------------
// K4: persistent ODE kernel. 128 CTAs x 512 threads; 16 rows/CTA.
// 2-way k-split: cg = tid&127 -> cols 2cg,2cg+1; rh = (tid>>7)&1 -> rows 8rh..;
// kh = tid>>8 -> k parity (stride-2 interleave within each weight block).
// Crossbar 32 cyc/k == FFMA2 issue 32 cyc/k, 4 warps/SMSP for latency hiding.
// ---------------------------------------------------------------------------
__device__ __forceinline__ void prefetch_w(uint32_t sdst, const float* gsrc, int tid) {
#pragma unroll
    for (int i = 0; i < WBYTES / (512 * 16); i++) {   // 4 x 16B per thread
        int off = (tid + i * 512) * 16;
        cp_async16(sdst + off, (const char*)gsrc + off);
    }
    cp_commit();
}

// one KB=32 block; this thread handles its k-parity half (16 k-indices)
__device__ __forceinline__ void gemm_block(uint32_t aBase, uint32_t wBase, U64 acc[2][4]) {
#pragma unroll
    for (int kk = 0; kk < 16; kk++) {
        U64 a0, a1, a2, a3;
        lds2x64(aBase + kk * (2 * MPB), a0, a1);
        lds2x64(aBase + kk * (2 * MPB) + 16, a2, a3);
        float w0f, w1f;
        lds2f(wBase + kk * 2048, w0f, w1f);
        U64 w0 = pack2(w0f, w0f), w1 = pack2(w1f, w1f);
        acc[0][0] = fma2(a0, w0, acc[0][0]); acc[0][1] = fma2(a1, w0, acc[0][1]);
        acc[0][2] = fma2(a2, w0, acc[0][2]); acc[0][3] = fma2(a3, w0, acc[0][3]);
        acc[1][0] = fma2(a0, w1, acc[1][0]); acc[1][1] = fma2(a1, w1, acc[1][1]);
        acc[1][2] = fma2(a2, w1, acc[1][2]); acc[1][3] = fma2(a3, w1, acc[1][3]);
    }
}

__device__ __forceinline__ void ldTile(uint32_t base, U64 t[2][4]) {
#pragma unroll
    for (int c = 0; c < 2; c++) {
        lds2x64(base + c * MPB, t[c][0], t[c][1]);
        lds2x64(base + c * MPB + 16, t[c][2], t[c][3]);
    }
}
__device__ __forceinline__ void stTile(uint32_t base, U64 t[2][4]) {
#pragma unroll
    for (int c = 0; c < 2; c++) {
        sts2x64(base + c * MPB, t[c][0], t[c][1]);
        sts2x64(base + c * MPB + 16, t[c][2], t[c][3]);
    }
}

// PS slot address for (cg, rh, quad j): [j][rh][cg] x 16B  (coalesced)
__device__ __forceinline__ uint32_t ps_addr(uint32_t psBase, int cg, int rh, int j) {
    return psBase + (uint32_t)(((j * 2 + rh) * 128 + cg) * 16);
}

__global__ void __launch_bounds__(512, 1)
ode_kernel(const int* __restrict__ lead_times, const int* __restrict__ nsp,
           const float* __restrict__ wl1, const float* __restrict__ bl1,
           const float* __restrict__ wl2, const float* __restrict__ bl2,
           const float* __restrict__ gn, const float* __restrict__ bn) {
    extern __shared__ __align__(16) float sm[];
    uint32_t sbase = (uint32_t)__cvta_generic_to_shared(sm);
    float* red = sm + OFF_RED / 4;   // [8 warps][8 rows] sums, +64 sqsums

    int tid = threadIdx.x;
    int cg = tid & 127;
    int rh = (tid >> 7) & 1;
    int kh = tid >> 8;
    int lane = tid & 31, warp = tid >> 5;
    int r0 = blockIdx.x * MROW;
    int steps = lead_times[r0 >> 8];
    int ns = nsp ? nsp[0] : 50;
    if (steps > ns) steps = ns;
    if (steps < 0) steps = 0;

    // per-thread packed constants for the 2 owned cols
    U64 bl1p[2], bl2p[2], gnp[2], bnp[2];
#pragma unroll
    for (int c = 0; c < 2; c++) {
        float v1 = bl1[2 * cg + c], v2 = bl2[2 * cg + c];
        float vg = gn[2 * cg + c],  vb = bn[2 * cg + c];
        bl1p[c] = kh ? 0ULL : pack2(v1, v1);
        bl2p[c] = kh ? 0ULL : pack2(v2, v2);
        gnp[c]  = pack2(vg, vg); bnp[c]  = pack2(vb, vb);
    }
    const U64 THREE = pack2(3.f, 3.f);
    const U64 DT8   = pack2(DT * 0.125f, DT * 0.125f);
    const U64 DT3   = pack2(DT * (1.f / 3.f), DT * (1.f / 3.f));
    const U64 DTP   = pack2(DT, DT);
    const U64 M3RD  = pack2(-1.f / 3.f, -1.f / 3.f);
    const U64 NEG1  = pack2(-1.f, -1.f);

    // load x1 -> ys (transposed [c][m])
    for (int idx = tid; idx < MROW * CDIM; idx += 512) {
        int c = idx & 255, m = idx >> 8;
        sm[OFF_YS / 4 + c * MP + m] = g_x1[(r0 + m) * CDIM + c];
    }
    __syncthreads();

    const uint32_t wb[2] = { sbase + OFF_W0, sbase + OFF_W1 };
    uint32_t psBase = sbase + OFF_PS;
    uint32_t colOff = (uint32_t)(2 * cg) * MPB + (uint32_t)rh * 32;  // epilogue tile
    uint32_t aRowK  = (uint32_t)rh * 32 + (uint32_t)kh * MPB;        // GEMM row base
    uint32_t wColK  = (uint32_t)cg * 8 + (uint32_t)kh * 1024;        // GEMM weight base

    // prime: block 0 -> buffer 0
    prefetch_w(wb[0], wl1, tid);

    for (int s = 0; s < steps; s++) {
        for (int st = 0; st < 4; st++) {
            uint32_t srcOff = (st == 0) ? (uint32_t)OFF_YS : (uint32_t)OFF_ARGS;
            uint32_t dstOff = (st == 0) ? (uint32_t)OFF_K1 : (st == 1) ? (uint32_t)OFF_K2
                             : (st == 2) ? (uint32_t)OFF_K3 : (uint32_t)OFF_YS;

            U64 acc[2][4];
            acc[0][0] = bl1p[0]; acc[0][1] = bl1p[0]; acc[0][2] = bl1p[0]; acc[0][3] = bl1p[0];
            acc[1][0] = bl1p[1]; acc[1][1] = bl1p[1]; acc[1][2] = bl1p[1]; acc[1][3] = bl1p[1];

            for (int p = 0; p < 16; p++) {
                // prefetch block p+1 (mod 16; periodic across fevals)
                int nb = (p + 1) & 15;
                const float* gsrc = (nb < 8) ? (wl1 + nb * (KB * CDIM))
                                             : (wl2 + (nb - 8) * (KB * CDIM));
                prefetch_w(wb[(p + 1) & 1], gsrc, tid);
                cp_wait1();
                __syncthreads();
                uint32_t aB = sbase + ((p < 8) ? srcOff : (uint32_t)OFF_H1)
                            + (uint32_t)(p & 7) * (KB * MPB) + aRowK;
                gemm_block(aB, wb[p & 1] + wColK, acc);

                if (p == 7) {
                    // k-split reduce GEMM1, then relu -> H1
                    if (kh) {
#pragma unroll
                        for (int j = 0; j < 4; j++)
                            sts2x64(ps_addr(psBase, cg, rh, j), acc[0][j], acc[1][j]);
                    }
                    __syncthreads();
                    if (!kh) {
#pragma unroll
                        for (int j = 0; j < 4; j++) {
                            U64 p0, p1;
                            lds2x64(ps_addr(psBase, cg, rh, j), p0, p1);
                            acc[0][j] = add2(acc[0][j], p0);
                            acc[1][j] = add2(acc[1][j], p1);
                        }
#pragma unroll
                        for (int c = 0; c < 2; c++) {
                            float f0, f1, f2, f3, f4, f5, f6, f7;
                            unpack2(acc[c][0], f0, f1); unpack2(acc[c][1], f2, f3);
                            unpack2(acc[c][2], f4, f5); unpack2(acc[c][3], f6, f7);
                            uint32_t hB = sbase + OFF_H1 + colOff + c * MPB;
                            sts4f(hB,      fmaxf(f0, 0.f), fmaxf(f1, 0.f), fmaxf(f2, 0.f), fmaxf(f3, 0.f));
                            sts4f(hB + 16, fmaxf(f4, 0.f), fmaxf(f5, 0.f), fmaxf(f6, 0.f), fmaxf(f7, 0.f));
                        }
                    }
                    // switch to GEMM2 accumulators
                    acc[0][0] = bl2p[0]; acc[0][1] = bl2p[0]; acc[0][2] = bl2p[0]; acc[0][3] = bl2p[0];
                    acc[1][0] = bl2p[1]; acc[1][1] = bl2p[1]; acc[1][2] = bl2p[1]; acc[1][3] = bl2p[1];
                    // H1 published by p=8's __syncthreads
                }
            }

            // ---- k-split reduce GEMM2 ----
            if (kh) {
#pragma unroll
                for (int j = 0; j < 4; j++)
                    sts2x64(ps_addr(psBase, cg, rh, j), acc[0][j], acc[1][j]);
            }
            __syncthreads();

            if (!kh) {
#pragma unroll
                for (int j = 0; j < 4; j++) {
                    U64 p0, p1;
                    lds2x64(ps_addr(psBase, cg, rh, j), p0, p1);
                    acc[0][j] = add2(acc[0][j], p0);
                    acc[1][j] = add2(acc[1][j], p1);
                }
                // residual
                U64 rs[2][4];
                ldTile(sbase + srcOff + colOff, rs);
#pragma unroll
                for (int c = 0; c < 2; c++)
#pragma unroll
                    for (int j = 0; j < 4; j++) acc[c][j] = add2(acc[c][j], rs[c][j]);

                float sv[8], qv[8];
#pragma unroll
                for (int j = 0; j < 4; j++) {
                    U64 S = add2(acc[0][j], acc[1][j]);
                    U64 Q = fma2(acc[1][j], acc[1][j], mul2(acc[0][j], acc[0][j]));
                    unpack2(S, sv[2 * j], sv[2 * j + 1]);
                    unpack2(Q, qv[2 * j], qv[2 * j + 1]);
                }
#pragma unroll
                for (int o = 16; o > 0; o >>= 1) {
#pragma unroll
                    for (int r = 0; r < 8; r++) {
                        sv[r] += __shfl_xor_sync(0xffffffffu, sv[r], o);
                        qv[r] += __shfl_xor_sync(0xffffffffu, qv[r], o);
                    }
                }
                if (lane == 0) {
#pragma unroll
                    for (int r = 0; r < 8; r++) {
                        red[warp * 8 + r] = sv[r];
                        red[64 + warp * 8 + r] = qv[r];
                    }
                }
            }
            __syncthreads();

            if (!kh) {
                float Af[8], Bf[8];
#pragma unroll
                for (int r = 0; r < 8; r++) {
                    int base = (rh * 4) * 8 + r;
                    float ts = red[base] + red[base + 8] + red[base + 16] + red[base + 24];
                    float tq = red[64 + base] + red[64 + base + 8] + red[64 + base + 16] + red[64 + base + 24];
                    float mean = ts * (1.f / 256.f);
                    float var  = tq * (1.f / 256.f) - mean * mean;
                    float rstd = rsqrtf(var + EPSLN);
                    Af[r] = rstd; Bf[r] = -mean * rstd;
                }
                U64 Ap[4], Bp[4];
#pragma unroll
                for (int j = 0; j < 4; j++) {
                    Ap[j] = pack2(Af[2 * j], Af[2 * j + 1]);
                    Bp[j] = pack2(Bf[2 * j], Bf[2 * j + 1]);
                }
                U64 kv[2][4];
#pragma unroll
                for (int c = 0; c < 2; c++)
#pragma unroll
                    for (int j = 0; j < 4; j++)
                        kv[c][j] = fma2(fma2(acc[c][j], Ap[j], Bp[j]), gnp[c], bnp[c]);

                if (st == 0) {
                    // residual source was y: arg = y + dt/3 * k1 (reload y per quad)
                    stTile(sbase + OFF_K1 + colOff, kv);
#pragma unroll
                    for (int c = 0; c < 2; c++) {
                        U64 ya, yb;
                        lds2x64(sbase + OFF_YS + colOff + c * MPB, ya, yb);
                        U64 a0 = fma2(kv[c][0], DT3, ya);
                        U64 a1 = fma2(kv[c][1], DT3, yb);
                        lds2x64(sbase + OFF_YS + colOff + c * MPB + 16, ya, yb);
                        U64 a2 = fma2(kv[c][2], DT3, ya);
                        U64 a3 = fma2(kv[c][3], DT3, yb);
                        sts2x64(sbase + OFF_ARGS + colOff + c * MPB, a0, a1);
                        sts2x64(sbase + OFF_ARGS + colOff + c * MPB + 16, a2, a3);
                    }
                } else if (st == 1) {
                    U64 yv[2][4], k1[2][4];
                    ldTile(sbase + OFF_YS + colOff, yv);
                    ldTile(sbase + OFF_K1 + colOff, k1);
                    stTile(sbase + OFF_K2 + colOff, kv);
                    U64 ar[2][4];
#pragma unroll
                    for (int c = 0; c < 2; c++)
#pragma unroll
                        for (int j = 0; j < 4; j++) {
                            U64 t = fma2(k1[c][j], M3RD, kv[c][j]);      // k2 - k1/3
                            ar[c][j] = fma2(t, DTP, yv[c][j]);
                        }
                    stTile(sbase + OFF_ARGS + colOff, ar);
                } else if (st == 2) {
                    U64 yv[2][4], k1[2][4], k2[2][4];
                    ldTile(sbase + OFF_YS + colOff, yv);
                    ldTile(sbase + OFF_K1 + colOff, k1);
                    ldTile(sbase + OFF_K2 + colOff, k2);
                    stTile(sbase + OFF_K3 + colOff, kv);
                    U64 ar[2][4];
#pragma unroll
                    for (int c = 0; c < 2; c++)
#pragma unroll
                        for (int j = 0; j < 4; j++) {
                            U64 t = add2(fma2(k2[c][j], NEG1, k1[c][j]), kv[c][j]); // k1-k2+k3
                            ar[c][j] = fma2(t, DTP, yv[c][j]);
                        }
                    stTile(sbase + OFF_ARGS + colOff, ar);
                } else {
                    U64 yv[2][4], k1[2][4], k2[2][4], k3[2][4];
                    ldTile(sbase + OFF_YS + colOff, yv);
                    ldTile(sbase + OFF_K1 + colOff, k1);
                    ldTile(sbase + OFF_K2 + colOff, k2);
                    ldTile(sbase + OFF_K3 + colOff, k3);
#pragma unroll
                    for (int c = 0; c < 2; c++)
#pragma unroll
                        for (int j = 0; j < 4; j++) {
                            U64 t = fma2(add2(k2[c][j], k3[c][j]), THREE, k1[c][j]);
                            t = add2(t, kv[c][j]);
                            yv[c][j] = fma2(t, DT8, yv[c][j]);
                        }
                    stTile(sbase + OFF_YS + colOff, yv);
                }
            }
            // next feval's first block barrier publishes these stores
        }
    }

    cp_wait_all();
    __syncthreads();
    for (int idx = tid; idx < MROW * CDIM; idx += 512) {
        int c = idx & 255, m = idx >> 8;
        g_ode[(r0 + m) * CDIM + c] = sm[OFF_YS / 4 + c * MP + m];
    }
}

// ---------------------------------------------------------------------------
// K5: out = LN(x1 + ode; g2,b2)
// ---------------------------------------------------------------------------
__global__ void final_ln_kernel(const float* __restrict__ g2,
                                const float* __restrict__ b2,
                                float* __restrict__ out) {
    int tid = threadIdx.x, lane = tid & 31, w = tid >> 5;
    int r = blockIdx.x * 8 + w;
    float v[8], ls = 0.f, lq = 0.f;
#pragma unroll
    for (int u = 0; u < 8; u++) {
        int c = lane + 32 * u;
        float t = g_x1[r * CDIM + c] + g_ode[r * CDIM + c];
        v[u] = t; ls += t; lq += t * t;
    }
#pragma unroll
    for (int o = 16; o > 0; o >>= 1) {
        ls += __shfl_xor_sync(0xffffffffu, ls, o);
        lq += __shfl_xor_sync(0xffffffffu, lq, o);
    }
    float mean = ls * (1.f / 256.f);
    float var  = lq * (1.f / 256.f) - mean * mean;
    float rstd = rsqrtf(var + EPSLN);
#pragma unroll
    for (int u = 0; u < 8; u++) {
        int c = lane + 32 * u;
        out[r * CDIM + c] = (v[u] - mean) * rstd * g2[c] + b2[c];
    }
}

// ---------------------------------------------------------------------------
// Launch
// ---------------------------------------------------------------------------
extern "C" void kernel_launch(void* const* d_in, const int* in_sizes, int n_in,
                              void* d_out, int out_size) {
    const float* x    = (const float*)d_in[0];
    const float* wqkv = (const float*)d_in[1];
    const float* bqkv = (const float*)d_in[2];
    const float* wo   = (const float*)d_in[3];
    const float* bo   = (const float*)d_in[4];
    const float* g1   = (const float*)d_in[5];
    const float* b1   = (const float*)d_in[6];
    const float* g2   = (const float*)d_in[7];
    const float* b2   = (const float*)d_in[8];
    const float* wl1  = (const float*)d_in[9];
    const float* bl1  = (const float*)d_in[10];
    const float* wl2  = (const float*)d_in[11];
    const float* bl2  = (const float*)d_in[12];
    const float* gn   = (const float*)d_in[13];
    const float* bn   = (const float*)d_in[14];
    const int* lead   = (const int*)d_in[15];
    const int* nsteps = (n_in > 16) ? (const int*)d_in[16] : nullptr;
    float* out = (float*)d_out;

    cudaFuncSetAttribute(attn_kernel, cudaFuncAttributeMaxDynamicSharedMemorySize, ATTN_SMEM);
    cudaFuncSetAttribute(ode_kernel, cudaFuncAttributeMaxDynamicSharedMemorySize, ODE_SMEM);

    qkv_kernel<<<dim3(64, 3), 256>>>(x, wqkv, bqkv);
    attn_kernel<<<64, 256, ATTN_SMEM>>>();
    proj_ln_kernel<<<64, 256>>>(x, wo, bo, g1, b1);
    ode_kernel<<<128, 512, ODE_SMEM>>>(lead, nsteps, wl1, bl1, wl2, bl2, gn, bn);
    final_ln_kernel<<<256, 256>>>(g2, b2, out);
}

// round 9
// speedup vs baseline: 2.6378x; 2.6378x over previous
#include <cuda_runtime.h>
#include <math.h>
#include <stdint.h>

#define EPSLN 1e-5f
#define DT    0.01f
#define CDIM  256
#define BDIM  8
#define NTOK  256
#define HEADS 8
#define HD    32
#define ROWS  (BDIM * NTOK)

#define RMJ   264   // row-major state stride (floats)

// ---- ODE smem layout (bytes) ----
#define OFF_YS   0
#define OFF_K1   16896
#define OFF_K2   33792
#define OFF_K3   50688
#define OFF_AR   67584
#define OFF_AST  84480     // A operand, fragment-native, 16 KB
#define OFF_W0   100864    // weight block buf0 (32 KB)
#define OFF_W1   133632    // weight block buf1 (32 KB)
#define OFF_RED  166400    // 256 floats
#define OFF_STAT 167424    // 32 floats
#define OFF_CST  167552    // bl1,bl2,gn,bn (4 KB)
#define ODE_SMEM 171648

// ---------------------------------------------------------------------------
// Scratch globals
// ---------------------------------------------------------------------------
__device__ float g_qbuf[3 * BDIM * HEADS * NTOK * HD];
__device__ float g_attnout[ROWS * CDIM];
__device__ float g_x1[ROWS * CDIM];
__device__ float g_ode[ROWS * CDIM];
// weights in MMA-B layout: [blk 0..7][kc 0..3][n 0..255][pair 0..3][slot 0..1]
__device__ float g_wt1[CDIM * CDIM];
__device__ float g_wt2[CDIM * CDIM];

// ---------------------------------------------------------------------------
// helpers
// ---------------------------------------------------------------------------
__device__ __forceinline__ uint32_t f2tf(float f) {
    uint32_t r; asm("cvt.rna.tf32.f32 %0, %1;" : "=r"(r) : "f"(f)); return r;
}
__device__ __forceinline__ void lds2u(uint32_t a, uint32_t& x, uint32_t& y) {
    asm volatile("ld.shared.v2.b32 {%0,%1}, [%2];" : "=r"(x), "=r"(y) : "r"(a));
}
__device__ __forceinline__ void sts1u(uint32_t a, uint32_t v) {
    asm volatile("st.shared.b32 [%0], %1;" :: "r"(a), "r"(v));
}
__device__ __forceinline__ void cp_async16(uint32_t sdst, const void* gsrc) {
    asm volatile("cp.async.cg.shared.global [%0], [%1], 16;" :: "r"(sdst), "l"(gsrc));
}
__device__ __forceinline__ void cp_commit() { asm volatile("cp.async.commit_group;"); }
__device__ __forceinline__ void cp_wait1() { asm volatile("cp.async.wait_group 1;" ::: "memory"); }
__device__ __forceinline__ void cp_wait0() { asm volatile("cp.async.wait_group 0;" ::: "memory"); }

__device__ __forceinline__ void mma_tf(float& c0, float& c1, float& c2, float& c3,
                                       uint32_t a0, uint32_t a1, uint32_t a2, uint32_t a3,
                                       uint32_t b0, uint32_t b1) {
    asm volatile(
        "mma.sync.aligned.m16n8k8.row.col.f32.tf32.tf32.f32 "
        "{%0,%1,%2,%3},{%4,%5,%6,%7},{%8,%9},{%0,%1,%2,%3};"
        : "+f"(c0), "+f"(c1), "+f"(c2), "+f"(c3)
        : "r"(a0), "r"(a1), "r"(a2), "r"(a3), "r"(b0), "r"(b1));
}

// A-stage byte offset for element (row r, col c)
__device__ __forceinline__ uint32_t astb(int r, int c) {
    return OFF_AST + (uint32_t)((c >> 3) * 512 + r * 32 + (c & 3) * 8 + ((c >> 2) & 1) * 4);
}

// ---------------------------------------------------------------------------
// prep: weights -> MMA-B layout (tf32-converted)
// ---------------------------------------------------------------------------
__global__ void prep_w_kernel(const float* __restrict__ wl1, const float* __restrict__ wl2) {
    int idx = blockIdx.x * 256 + threadIdx.x;   // 65536
    int k = idx >> 8, n = idx & 255;
    int dst = (k >> 5) * 8192 + ((k >> 3) & 3) * 2048 + n * 8 + (k & 3) * 2 + ((k >> 2) & 1);
    g_wt1[dst] = __uint_as_float(f2tf(wl1[k * 256 + n]));
    g_wt2[dst] = __uint_as_float(f2tf(wl2[k * 256 + n]));
}

// ---------------------------------------------------------------------------
// K1: qkv = x @ wqkv + bqkv
// ---------------------------------------------------------------------------
__global__ void qkv_kernel(const float* __restrict__ x, const float* __restrict__ wqkv,
                           const float* __restrict__ bqkv) {
    __shared__ __align__(16) float As[CDIM * 36];
    int tid = threadIdx.x, cg = tid & 31, rg = tid >> 5;
    int r0 = blockIdx.x * 32, cb = blockIdx.y;
    for (int idx = tid; idx < 32 * CDIM; idx += 256) {
        int c = idx & 255, m = idx >> 8;
        As[c * 36 + m] = x[(r0 + m) * CDIM + c];
    }
    __syncthreads();
    float acc[4][8];
#pragma unroll
    for (int j = 0; j < 8; j++) {
        float bv = bqkv[cb * 256 + cg + 32 * j];
#pragma unroll
        for (int mm = 0; mm < 4; mm++) acc[mm][j] = bv;
    }
    int m0 = rg * 4;
    const float* wp = wqkv + cb * 256 + cg;
#pragma unroll 4
    for (int k = 0; k < CDIM; k++) {
        float4 av = *(const float4*)(As + k * 36 + m0);
#pragma unroll
        for (int j = 0; j < 8; j++) {
            float w = wp[k * 768 + 32 * j];
            acc[0][j] = fmaf(av.x, w, acc[0][j]);
            acc[1][j] = fmaf(av.y, w, acc[1][j]);
            acc[2][j] = fmaf(av.z, w, acc[2][j]);
            acc[3][j] = fmaf(av.w, w, acc[3][j]);
        }
    }
#pragma unroll
    for (int mm = 0; mm < 4; mm++) {
        int r = r0 + m0 + mm, b = r >> 8, n = r & 255;
#pragma unroll
        for (int j = 0; j < 8; j++) {
            int cl = cg + 32 * j, h = cl >> 5, d = cl & 31;
            g_qbuf[(((cb * BDIM + b) * HEADS + h) * NTOK + n) * HD + d] = acc[mm][j];
        }
    }
}

// ---------------------------------------------------------------------------
// K2: attention
// ---------------------------------------------------------------------------
#define ATTN_SMEM ((3 * 256 * 33 + 8 * 256) * 4)
__global__ void attn_kernel() {
    extern __shared__ float sm[];
    float* qs = sm;
    float* ks = qs + 256 * 33;
    float* vs = ks + 256 * 33;
    float* prob = vs + 256 * 33;
    int tid = threadIdx.x, lane = tid & 31, w = tid >> 5;
    int bh = blockIdx.x, b = bh >> 3, h = bh & 7;
    const float scale = 0.17677669529663687f;
    const float* qg = g_qbuf + ((0 * BDIM + b) * HEADS + h) * NTOK * HD;
    const float* kg = g_qbuf + ((1 * BDIM + b) * HEADS + h) * NTOK * HD;
    const float* vg = g_qbuf + ((2 * BDIM + b) * HEADS + h) * NTOK * HD;
    for (int idx = tid; idx < NTOK * HD; idx += 256) {
        int n = idx >> 5, d = idx & 31;
        qs[n * 33 + d] = qg[idx] * scale;
        ks[n * 33 + d] = kg[idx];
        vs[n * 33 + d] = vg[idx];
    }
    __syncthreads();
    for (int n = w; n < NTOK; n += 8) {
        float s[8];
#pragma unroll
        for (int u = 0; u < 8; u++) {
            int j = lane + 32 * u;
            float a = 0.f;
#pragma unroll 8
            for (int d = 0; d < HD; d++) a = fmaf(qs[n * 33 + d], ks[j * 33 + d], a);
            s[u] = a;
        }
        float mx = s[0];
#pragma unroll
        for (int u = 1; u < 8; u++) mx = fmaxf(mx, s[u]);
#pragma unroll
        for (int o = 16; o > 0; o >>= 1) mx = fmaxf(mx, __shfl_xor_sync(0xffffffffu, mx, o));
        float sum = 0.f;
#pragma unroll
        for (int u = 0; u < 8; u++) { s[u] = __expf(s[u] - mx); sum += s[u]; }
#pragma unroll
        for (int o = 16; o > 0; o >>= 1) sum += __shfl_xor_sync(0xffffffffu, sum, o);
        float inv = 1.f / sum;
#pragma unroll
        for (int u = 0; u < 8; u++) prob[w * 256 + lane + 32 * u] = s[u] * inv;
        __syncwarp();
        float acc = 0.f;
#pragma unroll 8
        for (int j = 0; j < NTOK; j++) acc = fmaf(prob[w * 256 + j], vs[j * 33 + lane], acc);
        g_attnout[(b * NTOK + n) * CDIM + h * HD + lane] = acc;
        __syncwarp();
    }
}

// ---------------------------------------------------------------------------
// K3: x1 = LN(x + attnout @ wo + bo)
// ---------------------------------------------------------------------------
__global__ void proj_ln_kernel(const float* __restrict__ x, const float* __restrict__ wo,
                               const float* __restrict__ bo, const float* __restrict__ g1,
                               const float* __restrict__ b1) {
    __shared__ __align__(16) float As[CDIM * 36];
    int tid = threadIdx.x, cg = tid & 31, rg = tid >> 5;
    int r0 = blockIdx.x * 32;
    for (int idx = tid; idx < 32 * CDIM; idx += 256) {
        int c = idx & 255, m = idx >> 8;
        As[c * 36 + m] = g_attnout[(r0 + m) * CDIM + c];
    }
    __syncthreads();
    float acc[4][8];
#pragma unroll
    for (int j = 0; j < 8; j++) {
        float bv = bo[cg + 32 * j];
#pragma unroll
        for (int mm = 0; mm < 4; mm++) acc[mm][j] = bv;
    }
    int m0 = rg * 4;
    const float* wp = wo + cg;
#pragma unroll 4
    for (int k = 0; k < CDIM; k++) {
        float4 av = *(const float4*)(As + k * 36 + m0);
#pragma unroll
        for (int j = 0; j < 8; j++) {
            float w = wp[k * CDIM + 32 * j];
            acc[0][j] = fmaf(av.x, w, acc[0][j]);
            acc[1][j] = fmaf(av.y, w, acc[1][j]);
            acc[2][j] = fmaf(av.z, w, acc[2][j]);
            acc[3][j] = fmaf(av.w, w, acc[3][j]);
        }
    }
#pragma unroll
    for (int mm = 0; mm < 4; mm++) {
        int r = r0 + m0 + mm;
#pragma unroll
        for (int j = 0; j < 8; j++) acc[mm][j] += x[r * CDIM + cg + 32 * j];
        float ls = 0.f, lq = 0.f;
#pragma unroll
        for (int j = 0; j < 8; j++) { ls += acc[mm][j]; lq += acc[mm][j] * acc[mm][j]; }
#pragma unroll
        for (int o = 16; o > 0; o >>= 1) {
            ls += __shfl_xor_sync(0xffffffffu, ls, o);
            lq += __shfl_xor_sync(0xffffffffu, lq, o);
        }
        float mean = ls * (1.f / 256.f);
        float rstd = rsqrtf(lq * (1.f / 256.f) - mean * mean + EPSLN);
#pragma unroll
        for (int j = 0; j < 8; j++) {
            int c = cg + 32 * j;
            g_x1[r * CDIM + c] = (acc[mm][j] - mean) * rstd * g1[c] + b1[c];
        }
    }
}

// ---------------------------------------------------------------------------
// ODE kernel: 128 CTAs x 256 threads, 16 rows/CTA, tf32 mma.sync
// Warp w owns cols [32w, 32w+32): 4 n-tiles of m16n8.
// ---------------------------------------------------------------------------
__device__ __forceinline__ void prefB(uint32_t sdst, const float* gsrc, int tid) {
#pragma unroll
    for (int i = 0; i < 8; i++) {   // 32 KB / (256*16)
        int off = (tid + i * 256) * 16;
        cp_async16(sdst + off, (const char*)gsrc + off);
    }
    cp_commit();
}

__device__ __forceinline__ void run_gemm(uint32_t sbase, int gemmIdx, float acc[4][4],
                                         int warp, int lane, int tid) {
    int quad = lane >> 2, q = lane & 3;
#pragma unroll
    for (int t = 0; t < 4; t++)
#pragma unroll
        for (int j = 0; j < 4; j++) acc[t][j] = 0.f;
    uint32_t aBase = sbase + OFF_AST + (uint32_t)(quad * 32 + q * 8);
    uint32_t bBase = (uint32_t)(warp * 1024 + quad * 32 + q * 8);
    for (int p = 0; p < 8; p++) {
        int blk = gemmIdx * 8 + p;
        int nb = (blk + 1) & 15;
        const float* src = (nb < 8) ? g_wt1 + nb * 8192 : g_wt2 + (nb - 8) * 8192;
        prefB(sbase + ((nb & 1) ? OFF_W1 : OFF_W0), src, tid);
        cp_wait1();
        __syncthreads();
        uint32_t wb = sbase + ((blk & 1) ? OFF_W1 : OFF_W0) + bBase;
#pragma unroll
        for (int kc4 = 0; kc4 < 4; kc4++) {
            int kcg = p * 4 + kc4;
            uint32_t a0, a1, a2, a3;
            lds2u(aBase + kcg * 512, a0, a2);
            lds2u(aBase + kcg * 512 + 256, a1, a3);
            uint32_t bb = wb + kc4 * 8192;
#pragma unroll
            for (int t = 0; t < 4; t++) {
                uint32_t b0, b1;
                lds2u(bb + t * 256, b0, b1);
                mma_tf(acc[t][0], acc[t][1], acc[t][2], acc[t][3], a0, a1, a2, a3, b0, b1);
            }
        }
    }
}

template <int ST>
__device__ __forceinline__ void epi2(float* smF, uint32_t sbase, float acc[4][4],
                                     int warp, int lane, int tid) {
    int quad = lane >> 2, q = lane & 3;
    float* RES = smF + ((ST == 0) ? OFF_YS : OFF_AR) / 4;
    float* CST = smF + OFF_CST / 4;
    float* red = smF + OFF_RED / 4;
    float* stt = smF + OFF_STAT / 4;
    float v[4][4];
    float sl = 0.f, sh = 0.f, ql = 0.f, qh = 0.f;
#pragma unroll
    for (int t = 0; t < 4; t++) {
        int cb = warp * 32 + t * 8 + q * 2;
        float2 bias = *(float2*)(CST + 256 + cb);
        float2 rlo = *(float2*)(RES + quad * RMJ + cb);
        float2 rhi = *(float2*)(RES + (quad + 8) * RMJ + cb);
        float v00 = acc[t][0] + bias.x + rlo.x, v01 = acc[t][1] + bias.y + rlo.y;
        float v10 = acc[t][2] + bias.x + rhi.x, v11 = acc[t][3] + bias.y + rhi.y;
        v[t][0] = v00; v[t][1] = v01; v[t][2] = v10; v[t][3] = v11;
        sl += v00 + v01; ql += v00 * v00 + v01 * v01;
        sh += v10 + v11; qh += v10 * v10 + v11 * v11;
    }
#pragma unroll
    for (int o = 1; o < 4; o <<= 1) {
        sl += __shfl_xor_sync(0xffffffffu, sl, o);
        sh += __shfl_xor_sync(0xffffffffu, sh, o);
        ql += __shfl_xor_sync(0xffffffffu, ql, o);
        qh += __shfl_xor_sync(0xffffffffu, qh, o);
    }
    if (q == 0) {
        red[warp * 16 + quad] = sl;
        red[warp * 16 + quad + 8] = sh;
        red[128 + warp * 16 + quad] = ql;
        red[128 + warp * 16 + quad + 8] = qh;
    }
    __syncthreads();
    if (tid < 16) {
        float ts = 0.f, tq = 0.f;
#pragma unroll
        for (int w = 0; w < 8; w++) { ts += red[w * 16 + tid]; tq += red[128 + w * 16 + tid]; }
        float mean = ts * (1.f / 256.f);
        float rstd = rsqrtf(tq * (1.f / 256.f) - mean * mean + EPSLN);
        stt[tid] = rstd; stt[16 + tid] = -mean * rstd;
    }
    __syncthreads();
    float Al = stt[quad], Bl = stt[16 + quad];
    float Ah = stt[quad + 8], Bh = stt[16 + quad + 8];
    float* Y  = smF + OFF_YS / 4;
    float* K1 = smF + OFF_K1 / 4;
    float* K2 = smF + OFF_K2 / 4;
    float* K3 = smF + OFF_K3 / 4;
    float* AR = smF + OFF_AR / 4;
#pragma unroll
    for (int t = 0; t < 4; t++) {
        int cb = warp * 32 + t * 8 + q * 2;
        int ol = quad * RMJ + cb, oh = (quad + 8) * RMJ + cb;
        float2 gg = *(float2*)(CST + 512 + cb);
        float2 nn = *(float2*)(CST + 768 + cb);
        float k00 = (v[t][0] * Al + Bl) * gg.x + nn.x;
        float k01 = (v[t][1] * Al + Bl) * gg.y + nn.y;
        float k10 = (v[t][2] * Ah + Bh) * gg.x + nn.x;
        float k11 = (v[t][3] * Ah + Bh) * gg.y + nn.y;
        float2 ylo = *(float2*)(Y + ol), yhi = *(float2*)(Y + oh);
        float a00, a01, a10, a11;
        if (ST == 0) {
            *(float2*)(K1 + ol) = make_float2(k00, k01);
            *(float2*)(K1 + oh) = make_float2(k10, k11);
            const float c3 = DT * (1.f / 3.f);
            a00 = ylo.x + c3 * k00; a01 = ylo.y + c3 * k01;
            a10 = yhi.x + c3 * k10; a11 = yhi.y + c3 * k11;
        } else if (ST == 1) {
            float2 k1l = *(float2*)(K1 + ol), k1h = *(float2*)(K1 + oh);
            *(float2*)(K2 + ol) = make_float2(k00, k01);
            *(float2*)(K2 + oh) = make_float2(k10, k11);
            a00 = ylo.x + DT * (k00 - (1.f / 3.f) * k1l.x);
            a01 = ylo.y + DT * (k01 - (1.f / 3.f) * k1l.y);
            a10 = yhi.x + DT * (k10 - (1.f / 3.f) * k1h.x);
            a11 = yhi.y + DT * (k11 - (1.f / 3.f) * k1h.y);
        } else if (ST == 2) {
            float2 k1l = *(float2*)(K1 + ol), k1h = *(float2*)(K1 + oh);
            float2 k2l = *(float2*)(K2 + ol), k2h = *(float2*)(K2 + oh);
            *(float2*)(K3 + ol) = make_float2(k00, k01);
            *(float2*)(K3 + oh) = make_float2(k10, k11);
            a00 = ylo.x + DT * (k1l.x - k2l.x + k00);
            a01 = ylo.y + DT * (k1l.y - k2l.y + k01);
            a10 = yhi.x + DT * (k1h.x - k2h.x + k10);
            a11 = yhi.y + DT * (k1h.y - k2h.y + k11);
        } else {
            float2 k1l = *(float2*)(K1 + ol), k1h = *(float2*)(K1 + oh);
            float2 k2l = *(float2*)(K2 + ol), k2h = *(float2*)(K2 + oh);
            float2 k3l = *(float2*)(K3 + ol), k3h = *(float2*)(K3 + oh);
            a00 = ylo.x + (DT * 0.125f) * (k1l.x + 3.f * (k2l.x + k3l.x) + k00);
            a01 = ylo.y + (DT * 0.125f) * (k1l.y + 3.f * (k2l.y + k3l.y) + k01);
            a10 = yhi.x + (DT * 0.125f) * (k1h.x + 3.f * (k2h.x + k3h.x) + k10);
            a11 = yhi.y + (DT * 0.125f) * (k1h.y + 3.f * (k2h.y + k3h.y) + k11);
        }
        if (ST < 3) {
            *(float2*)(AR + ol) = make_float2(a00, a01);
            *(float2*)(AR + oh) = make_float2(a10, a11);
        } else {
            *(float2*)(Y + ol) = make_float2(a00, a01);
            *(float2*)(Y + oh) = make_float2(a10, a11);
        }
        sts1u(sbase + astb(quad, cb), f2tf(a00));
        sts1u(sbase + astb(quad, cb + 1), f2tf(a01));
        sts1u(sbase + astb(quad + 8, cb), f2tf(a10));
        sts1u(sbase + astb(quad + 8, cb + 1), f2tf(a11));
    }
}

__global__ void __launch_bounds__(256, 1)
ode_mma_kernel(const int* __restrict__ lead, const int* __restrict__ nsp,
               const float* __restrict__ bl1, const float* __restrict__ bl2,
               const float* __restrict__ gn, const float* __restrict__ bn) {
    extern __shared__ __align__(16) float smF[];
    uint32_t sbase;
    asm("{ .reg .u64 t; cvta.to.shared.u64 t, %1; cvt.u32.u64 %0, t; }"
        : "=r"(sbase) : "l"((const void*)smF));
    int tid = threadIdx.x, warp = tid >> 5, lane = tid & 31;
    int r0 = blockIdx.x * 16;
    int steps = lead[r0 >> 8];
    int ns = nsp ? nsp[0] : 50;
    if (steps > ns) steps = ns;
    if (steps < 0) steps = 0;

    float* CST = smF + OFF_CST / 4;
    for (int i = tid; i < 256; i += 256) {
        CST[i] = bl1[i]; CST[256 + i] = bl2[i];
        CST[512 + i] = gn[i]; CST[768 + i] = bn[i];
    }
    // x1 -> ys (row-major) + A-stage (tf32)
    for (int idx = tid; idx < 16 * 256; idx += 256) {
        int r = idx >> 8, c = idx & 255;
        float vv = g_x1[(r0 + r) * 256 + c];
        smF[OFF_YS / 4 + r * RMJ + c] = vv;
        sts1u(sbase + astb(r, c), f2tf(vv));
    }
    __syncthreads();

    prefB(sbase + OFF_W0, g_wt1, tid);   // prime block 0

    float acc[4][4];
    for (int s = 0; s < steps; s++) {
#pragma unroll 1
        for (int st = 0; st < 4; st++) {
            run_gemm(sbase, 0, acc, warp, lane, tid);
            __syncthreads();
            // epi1: h1 = relu(acc + bl1) -> A-stage
            {
                int quad = lane >> 2, q = lane & 3;
#pragma unroll
                for (int t = 0; t < 4; t++) {
                    int cb = warp * 32 + t * 8 + q * 2;
                    float2 bias = *(float2*)(CST + cb);
                    sts1u(sbase + astb(quad, cb),     f2tf(fmaxf(acc[t][0] + bias.x, 0.f)));
                    sts1u(sbase + astb(quad, cb + 1), f2tf(fmaxf(acc[t][1] + bias.y, 0.f)));
                    sts1u(sbase + astb(quad + 8, cb),     f2tf(fmaxf(acc[t][2] + bias.x, 0.f)));
                    sts1u(sbase + astb(quad + 8, cb + 1), f2tf(fmaxf(acc[t][3] + bias.y, 0.f)));
                }
            }
            run_gemm(sbase, 1, acc, warp, lane, tid);
            if (st == 0)      epi2<0>(smF, sbase, acc, warp, lane, tid);
            else if (st == 1) epi2<1>(smF, sbase, acc, warp, lane, tid);
            else if (st == 2) epi2<2>(smF, sbase, acc, warp, lane, tid);
            else              epi2<3>(smF, sbase, acc, warp, lane, tid);
            __syncthreads();
        }
    }
    cp_wait0();
    __syncthreads();
    for (int idx = tid; idx < 16 * 256; idx += 256) {
        int r = idx >> 8, c = idx & 255;
        g_ode[(r0 + r) * 256 + c] = smF[OFF_YS / 4 + r * RMJ + c];
    }
}

// ---------------------------------------------------------------------------
// K5: out = LN(x1 + ode; g2,b2)
// ---------------------------------------------------------------------------
__global__ void final_ln_kernel(const float* __restrict__ g2, const float* __restrict__ b2,
                                float* __restrict__ out) {
    int tid = threadIdx.x, lane = tid & 31, w = tid >> 5;
    int r = blockIdx.x * 8 + w;
    float v[8], ls = 0.f, lq = 0.f;
#pragma unroll
    for (int u = 0; u < 8; u++) {
        int c = lane + 32 * u;
        float t = g_x1[r * CDIM + c] + g_ode[r * CDIM + c];
        v[u] = t; ls += t; lq += t * t;
    }
#pragma unroll
    for (int o = 16; o > 0; o >>= 1) {
        ls += __shfl_xor_sync(0xffffffffu, ls, o);
        lq += __shfl_xor_sync(0xffffffffu, lq, o);
    }
    float mean = ls * (1.f / 256.f);
    float rstd = rsqrtf(lq * (1.f / 256.f) - mean * mean + EPSLN);
#pragma unroll
    for (int u = 0; u < 8; u++) {
        int c = lane + 32 * u;
        out[r * CDIM + c] = (v[u] - mean) * rstd * g2[c] + b2[c];
    }
}

// ---------------------------------------------------------------------------
// Launch
// ---------------------------------------------------------------------------
extern "C" void kernel_launch(void* const* d_in, const int* in_sizes, int n_in,
                              void* d_out, int out_size) {
    const float* x    = (const float*)d_in[0];
    const float* wqkv = (const float*)d_in[1];
    const float* bqkv = (const float*)d_in[2];
    const float* wo   = (const float*)d_in[3];
    const float* bo   = (const float*)d_in[4];
    const float* g1   = (const float*)d_in[5];
    const float* b1   = (const float*)d_in[6];
    const float* g2   = (const float*)d_in[7];
    const float* b2   = (const float*)d_in[8];
    const float* wl1  = (const float*)d_in[9];
    const float* bl1  = (const float*)d_in[10];
    const float* wl2  = (const float*)d_in[11];
    const float* bl2  = (const float*)d_in[12];
    const float* gn   = (const float*)d_in[13];
    const float* bn   = (const float*)d_in[14];
    const int* lead   = (const int*)d_in[15];
    const int* nsteps = (n_in > 16) ? (const int*)d_in[16] : nullptr;
    float* out = (float*)d_out;

    cudaFuncSetAttribute(attn_kernel, cudaFuncAttributeMaxDynamicSharedMemorySize, ATTN_SMEM);
    cudaFuncSetAttribute(ode_mma_kernel, cudaFuncAttributeMaxDynamicSharedMemorySize, ODE_SMEM);

    prep_w_kernel<<<256, 256>>>(wl1, wl2);
    qkv_kernel<<<dim3(64, 3), 256>>>(x, wqkv, bqkv);
    attn_kernel<<<64, 256, ATTN_SMEM>>>();
    proj_ln_kernel<<<64, 256>>>(x, wo, bo, g1, b1);
    ode_mma_kernel<<<128, 256, ODE_SMEM>>>(lead, nsteps, bl1, bl2, gn, bn);
    final_ln_kernel<<<256, 256>>>(g2, b2, out);
}

// round 11
// speedup vs baseline: 3.8947x; 1.4765x over previous
#include <cuda_runtime.h>
#include <math.h>
#include <stdint.h>

#define EPSLN 1e-5f
#define DT    0.01f
#define CDIM  256
#define BDIM  8
#define NTOK  256
#define HEADS 8
#define HD    32
#define ROWS  (BDIM * NTOK)

#define RMJ   264   // row-major state stride (floats)

// ---- ODE smem layout (bytes) ----
#define OFF_YS   0
#define OFF_K1   16896
#define OFF_K2   33792
#define OFF_K3   50688
#define OFF_AR   67584
#define OFF_AST  84480     // A operand bf16, fragment-native, 8 KB
#define OFF_W0   92672     // weight block buf0 (16 KB)
#define OFF_W1   109056    // weight block buf1 (16 KB)
#define OFF_RED  125440    // 256 floats
#define OFF_STAT 126464    // 32 floats
#define OFF_CST  126592    // bl1,bl2,gn,bn (4 KB)
#define ODE_SMEM 130688

// ---------------------------------------------------------------------------
// Scratch globals
// ---------------------------------------------------------------------------
__device__ float g_qbuf[3 * BDIM * HEADS * NTOK * HD];
__device__ float g_attnout[ROWS * CDIM];
__device__ float g_x1[ROWS * CDIM];
__device__ float g_ode[ROWS * CDIM];
// bf16-pair weights in MMA-B layout: [blk 0..7][cc 0..1][n 0..255][slot 0..7] u32
__device__ uint32_t g_wt1[CDIM * CDIM / 2];
__device__ uint32_t g_wt2[CDIM * CDIM / 2];

// ---------------------------------------------------------------------------
// helpers
// ---------------------------------------------------------------------------
__device__ __forceinline__ uint32_t f2bf2(float lo, float hi) {
    uint32_t r; asm("cvt.rn.bf16x2.f32 %0, %1, %2;" : "=r"(r) : "f"(hi), "f"(lo)); return r;
}
__device__ __forceinline__ void lds2u(uint32_t a, uint32_t& x, uint32_t& y) {
    asm volatile("ld.shared.v2.b32 {%0,%1}, [%2];" : "=r"(x), "=r"(y) : "r"(a));
}
__device__ __forceinline__ void sts1u(uint32_t a, uint32_t v) {
    asm volatile("st.shared.b32 [%0], %1;" :: "r"(a), "r"(v));
}
__device__ __forceinline__ void cp_async16(uint32_t sdst, const void* gsrc) {
    asm volatile("cp.async.cg.shared.global [%0], [%1], 16;" :: "r"(sdst), "l"(gsrc));
}
__device__ __forceinline__ void cp_commit() { asm volatile("cp.async.commit_group;"); }
__device__ __forceinline__ void cp_wait1() { asm volatile("cp.async.wait_group 1;" ::: "memory"); }
__device__ __forceinline__ void cp_wait0() { asm volatile("cp.async.wait_group 0;" ::: "memory"); }

__device__ __forceinline__ void mma_bf(float& c0, float& c1, float& c2, float& c3,
                                       uint32_t a0, uint32_t a1, uint32_t a2, uint32_t a3,
                                       uint32_t b0, uint32_t b1) {
    asm volatile(
        "mma.sync.aligned.m16n8k16.row.col.f32.bf16.bf16.f32 "
        "{%0,%1,%2,%3},{%4,%5,%6,%7},{%8,%9},{%0,%1,%2,%3};"
        : "+f"(c0), "+f"(c1), "+f"(c2), "+f"(c3)
        : "r"(a0), "r"(a1), "r"(a2), "r"(a3), "r"(b0), "r"(b1));
}

// A-stage byte offset for (row r, even col cb): pair pc=(cb>>1)&7, interleaved slots
__device__ __forceinline__ uint32_t astb2(int r, int cb) {
    int pc = (cb >> 1) & 7;
    return OFF_AST + (uint32_t)((cb >> 4) * 512 + r * 32 + ((pc & 3) * 2 + (pc >> 2)) * 4);
}

// ---------------------------------------------------------------------------
// prep: weights -> bf16-pair MMA-B layout
// ---------------------------------------------------------------------------
__global__ void prep_w_kernel(const float* __restrict__ wl1, const float* __restrict__ wl2) {
    int idx = blockIdx.x * 256 + threadIdx.x;   // 32768 total
    int kp = idx >> 8, n = idx & 255;           // kp = k-pair index 0..127
    int k = kp * 2;
    int pc = kp & 7;
    int dst = (k >> 5) * 4096 + ((k >> 4) & 1) * 2048 + n * 8 + (pc & 3) * 2 + (pc >> 2);
    g_wt1[dst] = f2bf2(wl1[k * 256 + n], wl1[(k + 1) * 256 + n]);
    g_wt2[dst] = f2bf2(wl2[k * 256 + n], wl2[(k + 1) * 256 + n]);
}

// ---------------------------------------------------------------------------
// K1: qkv = x @ wqkv + bqkv
// ---------------------------------------------------------------------------
__global__ void qkv_kernel(const float* __restrict__ x, const float* __restrict__ wqkv,
                           const float* __restrict__ bqkv) {
    __shared__ __align__(16) float As[CDIM * 36];
    int tid = threadIdx.x, cg = tid & 31, rg = tid >> 5;
    int r0 = blockIdx.x * 32, cb = blockIdx.y;
    for (int idx = tid; idx < 32 * CDIM; idx += 256) {
        int c = idx & 255, m = idx >> 8;
        As[c * 36 + m] = x[(r0 + m) * CDIM + c];
    }
    __syncthreads();
    float acc[4][8];
#pragma unroll
    for (int j = 0; j < 8; j++) {
        float bv = bqkv[cb * 256 + cg + 32 * j];
#pragma unroll
        for (int mm = 0; mm < 4; mm++) acc[mm][j] = bv;
    }
    int m0 = rg * 4;
    const float* wp = wqkv + cb * 256 + cg;
#pragma unroll 4
    for (int k = 0; k < CDIM; k++) {
        float4 av = *(const float4*)(As + k * 36 + m0);
#pragma unroll
        for (int j = 0; j < 8; j++) {
            float w = wp[k * 768 + 32 * j];
            acc[0][j] = fmaf(av.x, w, acc[0][j]);
            acc[1][j] = fmaf(av.y, w, acc[1][j]);
            acc[2][j] = fmaf(av.z, w, acc[2][j]);
            acc[3][j] = fmaf(av.w, w, acc[3][j]);
        }
    }
#pragma unroll
    for (int mm = 0; mm < 4; mm++) {
        int r = r0 + m0 + mm, b = r >> 8, n = r & 255;
#pragma unroll
        for (int j = 0; j < 8; j++) {
            int cl = cg + 32 * j, h = cl >> 5, d = cl & 31;
            g_qbuf[(((cb * BDIM + b) * HEADS + h) * NTOK + n) * HD + d] = acc[mm][j];
        }
    }
}

// ---------------------------------------------------------------------------
// K2: attention
// ---------------------------------------------------------------------------
#define ATTN_SMEM ((3 * 256 * 33 + 8 * 256) * 4)
__global__ void attn_kernel() {
    extern __shared__ float sm[];
    float* qs = sm;
    float* ks = qs + 256 * 33;
    float* vs = ks + 256 * 33;
    float* prob = vs + 256 * 33;
    int tid = threadIdx.x, lane = tid & 31, w = tid >> 5;
    int bh = blockIdx.x, b = bh >> 3, h = bh & 7;
    const float scale = 0.17677669529663687f;
    const float* qg = g_qbuf + ((0 * BDIM + b) * HEADS + h) * NTOK * HD;
    const float* kg = g_qbuf + ((1 * BDIM + b) * HEADS + h) * NTOK * HD;
    const float* vg = g_qbuf + ((2 * BDIM + b) * HEADS + h) * NTOK * HD;
    for (int idx = tid; idx < NTOK * HD; idx += 256) {
        int n = idx >> 5, d = idx & 31;
        qs[n * 33 + d] = qg[idx] * scale;
        ks[n * 33 + d] = kg[idx];
        vs[n * 33 + d] = vg[idx];
    }
    __syncthreads();
    for (int n = w; n < NTOK; n += 8) {
        float s[8];
#pragma unroll
        for (int u = 0; u < 8; u++) {
            int j = lane + 32 * u;
            float a = 0.f;
#pragma unroll 8
            for (int d = 0; d < HD; d++) a = fmaf(qs[n * 33 + d], ks[j * 33 + d], a);
            s[u] = a;
        }
        float mx = s[0];
#pragma unroll
        for (int u = 1; u < 8; u++) mx = fmaxf(mx, s[u]);
#pragma unroll
        for (int o = 16; o > 0; o >>= 1) mx = fmaxf(mx, __shfl_xor_sync(0xffffffffu, mx, o));
        float sum = 0.f;
#pragma unroll
        for (int u = 0; u < 8; u++) { s[u] = __expf(s[u] - mx); sum += s[u]; }
#pragma unroll
        for (int o = 16; o > 0; o >>= 1) sum += __shfl_xor_sync(0xffffffffu, sum, o);
        float inv = 1.f / sum;
#pragma unroll
        for (int u = 0; u < 8; u++) prob[w * 256 + lane + 32 * u] = s[u] * inv;
        __syncwarp();
        float acc = 0.f;
#pragma unroll 8
        for (int j = 0; j < NTOK; j++) acc = fmaf(prob[w * 256 + j], vs[j * 33 + lane], acc);
        g_attnout[(b * NTOK + n) * CDIM + h * HD + lane] = acc;
        __syncwarp();
    }
}

// ---------------------------------------------------------------------------
// K3: x1 = LN(x + attnout @ wo + bo)
// ---------------------------------------------------------------------------
__global__ void proj_ln_kernel(const float* __restrict__ x, const float* __restrict__ wo,
                               const float* __restrict__ bo, const float* __restrict__ g1,
                               const float* __restrict__ b1) {
    __shared__ __align__(16) float As[CDIM * 36];
    int tid = threadIdx.x, cg = tid & 31, rg = tid >> 5;
    int r0 = blockIdx.x * 32;
    for (int idx = tid; idx < 32 * CDIM; idx += 256) {
        int c = idx & 255, m = idx >> 8;
        As[c * 36 + m] = g_attnout[(r0 + m) * CDIM + c];
    }
    __syncthreads();
    float acc[4][8];
#pragma unroll
    for (int j = 0; j < 8; j++) {
        float bv = bo[cg + 32 * j];
#pragma unroll
        for (int mm = 0; mm < 4; mm++) acc[mm][j] = bv;
    }
    int m0 = rg * 4;
    const float* wp = wo + cg;
#pragma unroll 4
    for (int k = 0; k < CDIM; k++) {
        float4 av = *(const float4*)(As + k * 36 + m0);
#pragma unroll
        for (int j = 0; j < 8; j++) {
            float w = wp[k * CDIM + 32 * j];
            acc[0][j] = fmaf(av.x, w, acc[0][j]);
            acc[1][j] = fmaf(av.y, w, acc[1][j]);
            acc[2][j] = fmaf(av.z, w, acc[2][j]);
            acc[3][j] = fmaf(av.w, w, acc[3][j]);
        }
    }
#pragma unroll
    for (int mm = 0; mm < 4; mm++) {
        int r = r0 + m0 + mm;
#pragma unroll
        for (int j = 0; j < 8; j++) acc[mm][j] += x[r * CDIM + cg + 32 * j];
        float ls = 0.f, lq = 0.f;
#pragma unroll
        for (int j = 0; j < 8; j++) { ls += acc[mm][j]; lq += acc[mm][j] * acc[mm][j]; }
#pragma unroll
        for (int o = 16; o > 0; o >>= 1) {
            ls += __shfl_xor_sync(0xffffffffu, ls, o);
            lq += __shfl_xor_sync(0xffffffffu, lq, o);
        }
        float mean = ls * (1.f / 256.f);
        float rstd = rsqrtf(lq * (1.f / 256.f) - mean * mean + EPSLN);
#pragma unroll
        for (int j = 0; j < 8; j++) {
            int c = cg + 32 * j;
            g_x1[r * CDIM + c] = (acc[mm][j] - mean) * rstd * g1[c] + b1[c];
        }
    }
}

// ---------------------------------------------------------------------------
// ODE kernel: 128 CTAs x 256 threads, 16 rows/CTA, bf16 mma.sync m16n8k16
// Warp w owns cols [32w, 32w+32): 4 n-tiles of m16n8.
// ---------------------------------------------------------------------------
__device__ __forceinline__ void prefB(uint32_t sdst, const uint32_t* gsrc, int tid) {
#pragma unroll
    for (int i = 0; i < 4; i++) {   // 16 KB / (256*16)
        int off = (tid + i * 256) * 16;
        cp_async16(sdst + off, (const char*)gsrc + off);
    }
    cp_commit();
}

__device__ __forceinline__ void run_gemm(uint32_t sbase, int gemmIdx, float acc[4][4],
                                         int warp, int lane, int tid) {
    int quad = lane >> 2, q = lane & 3;
#pragma unroll
    for (int t = 0; t < 4; t++)
#pragma unroll
        for (int j = 0; j < 4; j++) acc[t][j] = 0.f;
    uint32_t aBase = sbase + OFF_AST + (uint32_t)(quad * 32 + q * 8);
    uint32_t bBase = (uint32_t)((warp * 32 + quad) * 32 + q * 8);
    for (int p = 0; p < 8; p++) {
        int blk = gemmIdx * 8 + p;
        int nb = (blk + 1) & 15;
        const uint32_t* src = (nb < 8) ? g_wt1 + nb * 4096 : g_wt2 + (nb - 8) * 4096;
        prefB(sbase + ((nb & 1) ? OFF_W1 : OFF_W0), src, tid);
        cp_wait1();
        __syncthreads();
        uint32_t wb = sbase + ((blk & 1) ? OFF_W1 : OFF_W0) + bBase;
#pragma unroll
        for (int cc = 0; cc < 2; cc++) {
            int c = p * 2 + cc;
            uint32_t a0, a1, a2, a3;
            lds2u(aBase + c * 512, a0, a2);
            lds2u(aBase + c * 512 + 256, a1, a3);
            uint32_t bb = wb + cc * 8192;
#pragma unroll
            for (int t = 0; t < 4; t++) {
                uint32_t b0, b1;
                lds2u(bb + t * 256, b0, b1);
                mma_bf(acc[t][0], acc[t][1], acc[t][2], acc[t][3], a0, a1, a2, a3, b0, b1);
            }
        }
    }
}

template <int ST>
__device__ __forceinline__ void epi2(float* smF, uint32_t sbase, float acc[4][4],
                                     int warp, int lane, int tid) {
    int quad = lane >> 2, q = lane & 3;
    float* RES = smF + ((ST == 0) ? OFF_YS : OFF_AR) / 4;
    float* CST = smF + OFF_CST / 4;
    float* red = smF + OFF_RED / 4;
    float* stt = smF + OFF_STAT / 4;
    float v[4][4];
    float sl = 0.f, sh = 0.f, ql = 0.f, qh = 0.f;
#pragma unroll
    for (int t = 0; t < 4; t++) {
        int cb = warp * 32 + t * 8 + q * 2;
        float2 bias = *(float2*)(CST + 256 + cb);
        float2 rlo = *(float2*)(RES + quad * RMJ + cb);
        float2 rhi = *(float2*)(RES + (quad + 8) * RMJ + cb);
        float v00 = acc[t][0] + bias.x + rlo.x, v01 = acc[t][1] + bias.y + rlo.y;
        float v10 = acc[t][2] + bias.x + rhi.x, v11 = acc[t][3] + bias.y + rhi.y;
        v[t][0] = v00; v[t][1] = v01; v[t][2] = v10; v[t][3] = v11;
        sl += v00 + v01; ql += v00 * v00 + v01 * v01;
        sh += v10 + v11; qh += v10 * v10 + v11 * v11;
    }
#pragma unroll
    for (int o = 1; o < 4; o <<= 1) {
        sl += __shfl_xor_sync(0xffffffffu, sl, o);
        sh += __shfl_xor_sync(0xffffffffu, sh, o);
        ql += __shfl_xor_sync(0xffffffffu, ql, o);
        qh += __shfl_xor_sync(0xffffffffu, qh, o);
    }
    if (q == 0) {
        red[warp * 16 + quad] = sl;
        red[warp * 16 + quad + 8] = sh;
        red[128 + warp * 16 + quad] = ql;
        red[128 + warp * 16 + quad + 8] = qh;
    }
    __syncthreads();
    if (tid < 16) {
        float ts = 0.f, tq = 0.f;
#pragma unroll
        for (int w = 0; w < 8; w++) { ts += red[w * 16 + tid]; tq += red[128 + w * 16 + tid]; }
        float mean = ts * (1.f / 256.f);
        float rstd = rsqrtf(tq * (1.f / 256.f) - mean * mean + EPSLN);
        stt[tid] = rstd; stt[16 + tid] = -mean * rstd;
    }
    __syncthreads();
    float Al = stt[quad], Bl = stt[16 + quad];
    float Ah = stt[quad + 8], Bh = stt[16 + quad + 8];
    float* Y  = smF + OFF_YS / 4;
    float* K1 = smF + OFF_K1 / 4;
    float* K2 = smF + OFF_K2 / 4;
    float* K3 = smF + OFF_K3 / 4;
    float* AR = smF + OFF_AR / 4;
#pragma unroll
    for (int t = 0; t < 4; t++) {
        int cb = warp * 32 + t * 8 + q * 2;
        int ol = quad * RMJ + cb, oh = (quad + 8) * RMJ + cb;
        float2 gg = *(float2*)(CST + 512 + cb);
        float2 nn = *(float2*)(CST + 768 + cb);
        float k00 = (v[t][0] * Al + Bl) * gg.x + nn.x;
        float k01 = (v[t][1] * Al + Bl) * gg.y + nn.y;
        float k10 = (v[t][2] * Ah + Bh) * gg.x + nn.x;
        float k11 = (v[t][3] * Ah + Bh) * gg.y + nn.y;
        float2 ylo = *(float2*)(Y + ol), yhi = *(float2*)(Y + oh);
        float a00, a01, a10, a11;
        if (ST == 0) {
            *(float2*)(K1 + ol) = make_float2(k00, k01);
            *(float2*)(K1 + oh) = make_float2(k10, k11);
            const float c3 = DT * (1.f / 3.f);
            a00 = ylo.x + c3 * k00; a01 = ylo.y + c3 * k01;
            a10 = yhi.x + c3 * k10; a11 = yhi.y + c3 * k11;
        } else if (ST == 1) {
            float2 k1l = *(float2*)(K1 + ol), k1h = *(float2*)(K1 + oh);
            *(float2*)(K2 + ol) = make_float2(k00, k01);
            *(float2*)(K2 + oh) = make_float2(k10, k11);
            a00 = ylo.x + DT * (k00 - (1.f / 3.f) * k1l.x);
            a01 = ylo.y + DT * (k01 - (1.f / 3.f) * k1l.y);
            a10 = yhi.x + DT * (k10 - (1.f / 3.f) * k1h.x);
            a11 = yhi.y + DT * (k11 - (1.f / 3.f) * k1h.y);
        } else if (ST == 2) {
            float2 k1l = *(float2*)(K1 + ol), k1h = *(float2*)(K1 + oh);
            float2 k2l = *(float2*)(K2 + ol), k2h = *(float2*)(K2 + oh);
            *(float2*)(K3 + ol) = make_float2(k00, k01);
            *(float2*)(K3 + oh) = make_float2(k10, k11);
            a00 = ylo.x + DT * (k1l.x - k2l.x + k00);
            a01 = ylo.y + DT * (k1l.y - k2l.y + k01);
            a10 = yhi.x + DT * (k1h.x - k2h.x + k10);
            a11 = yhi.y + DT * (k1h.y - k2h.y + k11);
        } else {
            float2 k1l = *(float2*)(K1 + ol), k1h = *(float2*)(K1 + oh);
            float2 k2l = *(float2*)(K2 + ol), k2h = *(float2*)(K2 + oh);
            float2 k3l = *(float2*)(K3 + ol), k3h = *(float2*)(K3 + oh);
            a00 = ylo.x + (DT * 0.125f) * (k1l.x + 3.f * (k2l.x + k3l.x) + k00);
            a01 = ylo.y + (DT * 0.125f) * (k1l.y + 3.f * (k2l.y + k3l.y) + k01);
            a10 = yhi.x + (DT * 0.125f) * (k1h.x + 3.f * (k2h.x + k3h.x) + k10);
            a11 = yhi.y + (DT * 0.125f) * (k1h.y + 3.f * (k2h.y + k3h.y) + k11);
        }
        if (ST < 3) {
            *(float2*)(AR + ol) = make_float2(a00, a01);
            *(float2*)(AR + oh) = make_float2(a10, a11);
        } else {
            *(float2*)(Y + ol) = make_float2(a00, a01);
            *(float2*)(Y + oh) = make_float2(a10, a11);
        }
        sts1u(sbase + astb2(quad, cb), f2bf2(a00, a01));
        sts1u(sbase + astb2(quad + 8, cb), f2bf2(a10, a11));
    }
}

__global__ void __launch_bounds__(256, 1)
ode_mma_kernel(const int* __restrict__ lead, const int* __restrict__ nsp,
               const float* __restrict__ bl1, const float* __restrict__ bl2,
               const float* __restrict__ gn, const float* __restrict__ bn) {
    extern __shared__ __align__(16) float smF[];
    uint32_t sbase;
    asm("{ .reg .u64 t; cvta.to.shared.u64 t, %1; cvt.u32.u64 %0, t; }"
        : "=r"(sbase) : "l"((const void*)smF));
    int tid = threadIdx.x, warp = tid >> 5, lane = tid & 31;
    int r0 = blockIdx.x * 16;
    int steps = lead[r0 >> 8];
    int ns = nsp ? nsp[0] : 50;
    if (steps > ns) steps = ns;
    if (steps < 0) steps = 0;

    float* CST = smF + OFF_CST / 4;
    for (int i = tid; i < 256; i += 256) {
        CST[i] = bl1[i]; CST[256 + i] = bl2[i];
        CST[512 + i] = gn[i]; CST[768 + i] = bn[i];
    }
    // x1 -> ys (row-major fp32) + A-stage (bf16 pairs)
    for (int idx = tid; idx < 16 * 128; idx += 256) {
        int r = idx >> 7, kp = idx & 127;
        int cb = kp * 2;
        float2 vv = *(const float2*)(g_x1 + (r0 + r) * 256 + cb);
        smF[OFF_YS / 4 + r * RMJ + cb] = vv.x;
        smF[OFF_YS / 4 + r * RMJ + cb + 1] = vv.y;
        sts1u(sbase + astb2(r, cb), f2bf2(vv.x, vv.y));
    }
    __syncthreads();

    prefB(sbase + OFF_W0, g_wt1, tid);   // prime block 0

    float acc[4][4];
    for (int s = 0; s < steps; s++) {
#pragma unroll 1
        for (int st = 0; st < 4; st++) {
            run_gemm(sbase, 0, acc, warp, lane, tid);
            __syncthreads();
            // epi1: h1 = relu(acc + bl1) -> A-stage (bf16)
            {
                int quad = lane >> 2, q = lane & 3;
#pragma unroll
                for (int t = 0; t < 4; t++) {
                    int cb = warp * 32 + t * 8 + q * 2;
                    float2 bias = *(float2*)(CST + cb);
                    sts1u(sbase + astb2(quad, cb),
                          f2bf2(fmaxf(acc[t][0] + bias.x, 0.f), fmaxf(acc[t][1] + bias.y, 0.f)));
                    sts1u(sbase + astb2(quad + 8, cb),
                          f2bf2(fmaxf(acc[t][2] + bias.x, 0.f), fmaxf(acc[t][3] + bias.y, 0.f)));
                }
            }
            run_gemm(sbase, 1, acc, warp, lane, tid);
            if (st == 0)      epi2<0>(smF, sbase, acc, warp, lane, tid);
            else if (st == 1) epi2<1>(smF, sbase, acc, warp, lane, tid);
            else if (st == 2) epi2<2>(smF, sbase, acc, warp, lane, tid);
            else              epi2<3>(smF, sbase, acc, warp, lane, tid);
            __syncthreads();
        }
    }
    cp_wait0();
    __syncthreads();
    for (int idx = tid; idx < 16 * 256; idx += 256) {
        int r = idx >> 8, c = idx & 255;
        g_ode[(r0 + r) * 256 + c] = smF[OFF_YS / 4 + r * RMJ + c];
    }
}

// ---------------------------------------------------------------------------
// K5: out = LN(x1 + ode; g2,b2)
// ---------------------------------------------------------------------------
__global__ void final_ln_kernel(const float* __restrict__ g2, const float* __restrict__ b2,
                                float* __restrict__ out) {
    int tid = threadIdx.x, lane = tid & 31, w = tid >> 5;
    int r = blockIdx.x * 8 + w;
    float v[8], ls = 0.f, lq = 0.f;
#pragma unroll
    for (int u = 0; u < 8; u++) {
        int c = lane + 32 * u;
        float t = g_x1[r * CDIM + c] + g_ode[r * CDIM + c];
        v[u] = t; ls += t; lq += t * t;
    }
#pragma unroll
    for (int o = 16; o > 0; o >>= 1) {
        ls += __shfl_xor_sync(0xffffffffu, ls, o);
        lq += __shfl_xor_sync(0xffffffffu, lq, o);
    }
    float mean = ls * (1.f / 256.f);
    float rstd = rsqrtf(lq * (1.f / 256.f) - mean * mean + EPSLN);
#pragma unroll
    for (int u = 0; u < 8; u++) {
        int c = lane + 32 * u;
        out[r * CDIM + c] = (v[u] - mean) * rstd * g2[c] + b2[c];
    }
}

// ---------------------------------------------------------------------------
// Launch
// ---------------------------------------------------------------------------
extern "C" void kernel_launch(void* const* d_in, const int* in_sizes, int n_in,
                              void* d_out, int out_size) {
    const float* x    = (const float*)d_in[0];
    const float* wqkv = (const float*)d_in[1];
    const float* bqkv = (const float*)d_in[2];
    const float* wo   = (const float*)d_in[3];
    const float* bo   = (const float*)d_in[4];
    const float* g1   = (const float*)d_in[5];
    const float* b1   = (const float*)d_in[6];
    const float* g2   = (const float*)d_in[7];
    const float* b2   = (const float*)d_in[8];
    const float* wl1  = (const float*)d_in[9];
    const float* bl1  = (const float*)d_in[10];
    const float* wl2  = (const float*)d_in[11];
    const float* bl2  = (const float*)d_in[12];
    const float* gn   = (const float*)d_in[13];
    const float* bn   = (const float*)d_in[14];
    const int* lead   = (const int*)d_in[15];
    const int* nsteps = (n_in > 16) ? (const int*)d_in[16] : nullptr;
    float* out = (float*)d_out;

    cudaFuncSetAttribute(attn_kernel, cudaFuncAttributeMaxDynamicSharedMemorySize, ATTN_SMEM);
    cudaFuncSetAttribute(ode_mma_kernel, cudaFuncAttributeMaxDynamicSharedMemorySize, ODE_SMEM);

    prep_w_kernel<<<128, 256>>>(wl1, wl2);
    qkv_kernel<<<dim3(64, 3), 256>>>(x, wqkv, bqkv);
    attn_kernel<<<64, 256, ATTN_SMEM>>>();
    proj_ln_kernel<<<64, 256>>>(x, wo, bo, g1, b1);
    ode_mma_kernel<<<128, 256, ODE_SMEM>>>(lead, nsteps, bl1, bl2, gn, bn);
    final_ln_kernel<<<256, 256>>>(g2, b2, out);
}

// round 12
// speedup vs baseline: 4.3818x; 1.1251x over previous
#include <cuda_runtime.h>
#include <math.h>
#include <stdint.h>

#define EPSLN 1e-5f
#define DT    0.01f
#define CDIM  256
#define BDIM  8
#define NTOK  256
#define HEADS 8
#define HD    32
#define ROWS  (BDIM * NTOK)

#define RMJ   264   // row-major state stride (floats)

// ---- ODE smem layout (bytes) ----
#define OFF_YS   0
#define OFF_K1   16896
#define OFF_K2   33792
#define OFF_K3   50688
#define OFF_AR   67584
#define OFF_AST  84480     // A operand bf16, fragment-native, 8 KB
#define OFF_W0   92672     // weight block buf0 (16 KB)
#define OFF_W1   109056    // weight block buf1 (16 KB)
#define OFF_RED  125440    // 256 floats
#define OFF_STAT 126464    // 32 floats
#define OFF_CST  126592    // bl1,bl2,gn,bn (4 KB)
#define ODE_SMEM 130688

// ---- prologue mma kernels smem layout (bytes) ----
#define P_AST    0          // 16 KB tf32 A-stage
#define P_W0     16384      // 32 KB
#define P_W1     49152      // 32 KB
#define P_RED    81920      // 256 floats
#define P_STAT   82944      // 32 floats
#define QKV_SMEM 81920
#define PROJ_SMEM 83072

// ---------------------------------------------------------------------------
// Scratch globals
// ---------------------------------------------------------------------------
__device__ float g_qbuf[3 * BDIM * HEADS * NTOK * HD];
__device__ float g_attnout[ROWS * CDIM];
__device__ float g_x1[ROWS * CDIM];
__device__ float g_ode[ROWS * CDIM];
// bf16-pair ODE weights in MMA-B layout
__device__ uint32_t g_wt1[CDIM * CDIM / 2];
__device__ uint32_t g_wt2[CDIM * CDIM / 2];
// tf32 MMA-B layout prologue weights
__device__ float g_wqkv_t[CDIM * 768];
__device__ float g_wo_t[CDIM * CDIM];

// ---------------------------------------------------------------------------
// helpers
// ---------------------------------------------------------------------------
__device__ __forceinline__ uint32_t f2bf2(float lo, float hi) {
    uint32_t r; asm("cvt.rn.bf16x2.f32 %0, %1, %2;" : "=r"(r) : "f"(hi), "f"(lo)); return r;
}
__device__ __forceinline__ uint32_t f2tf(float f) {
    uint32_t r; asm("cvt.rna.tf32.f32 %0, %1;" : "=r"(r) : "f"(f)); return r;
}
__device__ __forceinline__ void lds2u(uint32_t a, uint32_t& x, uint32_t& y) {
    asm volatile("ld.shared.v2.b32 {%0,%1}, [%2];" : "=r"(x), "=r"(y) : "r"(a));
}
__device__ __forceinline__ void sts1u(uint32_t a, uint32_t v) {
    asm volatile("st.shared.b32 [%0], %1;" :: "r"(a), "r"(v));
}
__device__ __forceinline__ void cp_async16(uint32_t sdst, const void* gsrc) {
    asm volatile("cp.async.cg.shared.global [%0], [%1], 16;" :: "r"(sdst), "l"(gsrc));
}
__device__ __forceinline__ void cp_commit() { asm volatile("cp.async.commit_group;"); }
__device__ __forceinline__ void cp_wait1() { asm volatile("cp.async.wait_group 1;" ::: "memory"); }
__device__ __forceinline__ void cp_wait0() { asm volatile("cp.async.wait_group 0;" ::: "memory"); }

__device__ __forceinline__ void mma_bf(float& c0, float& c1, float& c2, float& c3,
                                       uint32_t a0, uint32_t a1, uint32_t a2, uint32_t a3,
                                       uint32_t b0, uint32_t b1) {
    asm volatile(
        "mma.sync.aligned.m16n8k16.row.col.f32.bf16.bf16.f32 "
        "{%0,%1,%2,%3},{%4,%5,%6,%7},{%8,%9},{%0,%1,%2,%3};"
        : "+f"(c0), "+f"(c1), "+f"(c2), "+f"(c3)
        : "r"(a0), "r"(a1), "r"(a2), "r"(a3), "r"(b0), "r"(b1));
}
__device__ __forceinline__ void mma_tf(float& c0, float& c1, float& c2, float& c3,
                                       uint32_t a0, uint32_t a1, uint32_t a2, uint32_t a3,
                                       uint32_t b0, uint32_t b1) {
    asm volatile(
        "mma.sync.aligned.m16n8k8.row.col.f32.tf32.tf32.f32 "
        "{%0,%1,%2,%3},{%4,%5,%6,%7},{%8,%9},{%0,%1,%2,%3};"
        : "+f"(c0), "+f"(c1), "+f"(c2), "+f"(c3)
        : "r"(a0), "r"(a1), "r"(a2), "r"(a3), "r"(b0), "r"(b1));
}

// bf16 A-stage byte offset (ODE)
__device__ __forceinline__ uint32_t astb2(int r, int cb) {
    int pc = (cb >> 1) & 7;
    return OFF_AST + (uint32_t)((cb >> 4) * 512 + r * 32 + ((pc & 3) * 2 + (pc >> 2)) * 4);
}
// tf32 A-stage byte offset (prologue)
__device__ __forceinline__ uint32_t astf(int r, int c) {
    return P_AST + (uint32_t)((c >> 3) * 512 + r * 32 + (c & 3) * 8 + ((c >> 2) & 1) * 4);
}

// ---------------------------------------------------------------------------
// prep: ODE weights -> bf16-pair MMA-B layout
// ---------------------------------------------------------------------------
__global__ void prep_w_kernel(const float* __restrict__ wl1, const float* __restrict__ wl2) {
    int idx = blockIdx.x * 256 + threadIdx.x;
    int kp = idx >> 8, n = idx & 255;
    int k = kp * 2;
    int pc = kp & 7;
    int dst = (k >> 5) * 4096 + ((k >> 4) & 1) * 2048 + n * 8 + (pc & 3) * 2 + (pc >> 2);
    g_wt1[dst] = f2bf2(wl1[k * 256 + n], wl1[(k + 1) * 256 + n]);
    g_wt2[dst] = f2bf2(wl2[k * 256 + n], wl2[(k + 1) * 256 + n]);
}

// prep: prologue weights -> tf32 MMA-B layout
__global__ void prep_qkv_kernel(const float* __restrict__ wqkv) {
    int k = blockIdx.x, n = threadIdx.x, g = blockIdx.y;
    int dst = g * 65536 + (k >> 5) * 8192 + ((k >> 3) & 3) * 2048 + n * 8 + (k & 3) * 2 + ((k >> 2) & 1);
    g_wqkv_t[dst] = __uint_as_float(f2tf(wqkv[k * 768 + g * 256 + n]));
}
__global__ void prep_wo_kernel(const float* __restrict__ wo) {
    int k = blockIdx.x, n = threadIdx.x;
    int dst = (k >> 5) * 8192 + ((k >> 3) & 3) * 2048 + n * 8 + (k & 3) * 2 + ((k >> 2) & 1);
    g_wo_t[dst] = __uint_as_float(f2tf(wo[k * 256 + n]));
}

// ---------------------------------------------------------------------------
// prologue tf32 GEMM core (R9-proven layouts): acc[4][4] += A16x256 @ W256x(warp cols)
// ---------------------------------------------------------------------------
__device__ __forceinline__ void prefB32(uint32_t sdst, const float* gsrc, int tid) {
#pragma unroll
    for (int i = 0; i < 8; i++) {
        int off = (tid + i * 256) * 16;
        cp_async16(sdst + off, (const char*)gsrc + off);
    }
    cp_commit();
}

__device__ __forceinline__ void run_gemm_tf(uint32_t sbase, const float* gw,
                                            float acc[4][4], int warp, int lane, int tid) {
    int quad = lane >> 2, q = lane & 3;
#pragma unroll
    for (int t = 0; t < 4; t++)
#pragma unroll
        for (int j = 0; j < 4; j++) acc[t][j] = 0.f;
    uint32_t aBase = sbase + P_AST + (uint32_t)(quad * 32 + q * 8);
    uint32_t bBase = (uint32_t)(warp * 1024 + quad * 32 + q * 8);
    for (int p = 0; p < 8; p++) {
        if (p < 7) {
            prefB32(sbase + (((p + 1) & 1) ? P_W1 : P_W0), gw + (p + 1) * 8192, tid);
            cp_wait1();
        } else {
            cp_wait0();
        }
        __syncthreads();
        uint32_t wb = sbase + ((p & 1) ? P_W1 : P_W0) + bBase;
#pragma unroll
        for (int kc4 = 0; kc4 < 4; kc4++) {
            int kcg = p * 4 + kc4;
            uint32_t a0, a1, a2, a3;
            lds2u(aBase + kcg * 512, a0, a2);
            lds2u(aBase + kcg * 512 + 256, a1, a3);
            uint32_t bb = wb + kc4 * 8192;
#pragma unroll
            for (int t = 0; t < 4; t++) {
                uint32_t b0, b1;
                lds2u(bb + t * 256, b0, b1);
                mma_tf(acc[t][0], acc[t][1], acc[t][2], acc[t][3], a0, a1, a2, a3, b0, b1);
            }
        }
    }
}

// ---------------------------------------------------------------------------
// K1: qkv via tf32 mma. grid (128, 3), 256 thr.
// ---------------------------------------------------------------------------
__global__ void __launch_bounds__(256, 1)
qkv_mma_kernel(const float* __restrict__ x, const float* __restrict__ bqkv) {
    extern __shared__ __align__(16) float smF[];
    uint32_t sbase;
    asm("{ .reg .u64 t; cvta.to.shared.u64 t, %1; cvt.u32.u64 %0, t; }"
        : "=r"(sbase) : "l"((const void*)smF));
    int tid = threadIdx.x, warp = tid >> 5, lane = tid & 31;
    int r0 = blockIdx.x * 16, g = blockIdx.y;

    for (int idx = tid; idx < 16 * 256; idx += 256) {
        int r = idx >> 8, c = idx & 255;
        sts1u(sbase + astf(r, c), f2tf(x[(r0 + r) * 256 + c]));
    }
    prefB32(sbase + P_W0, g_wqkv_t + g * 65536, tid);

    float acc[4][4];
    run_gemm_tf(sbase, g_wqkv_t + g * 65536, acc, warp, lane, tid);

    int quad = lane >> 2, q = lane & 3;
#pragma unroll
    for (int t = 0; t < 4; t++) {
        int cb = warp * 32 + t * 8 + q * 2;
        float2 bias = *(const float2*)(bqkv + g * 256 + cb);
        int h = cb >> 5, d = cb & 31;
#pragma unroll
        for (int half = 0; half < 2; half++) {
            int r = r0 + quad + half * 8;
            int b = r >> 8, n = r & 255;
            float2 ov;
            ov.x = acc[t][2 * half + 0] + bias.x;
            ov.y = acc[t][2 * half + 1] + bias.y;
            *(float2*)(g_qbuf + (((g * BDIM + b) * HEADS + h) * NTOK + n) * HD + d) = ov;
        }
    }
}

// ---------------------------------------------------------------------------
// K2: attention (unchanged)
// ---------------------------------------------------------------------------
#define ATTN_SMEM ((3 * 256 * 33 + 8 * 256) * 4)
__global__ void attn_kernel() {
    extern __shared__ float sm[];
    float* qs = sm;
    float* ks = qs + 256 * 33;
    float* vs = ks + 256 * 33;
    float* prob = vs + 256 * 33;
    int tid = threadIdx.x, lane = tid & 31, w = tid >> 5;
    int bh = blockIdx.x, b = bh >> 3, h = bh & 7;
    const float scale = 0.17677669529663687f;
    const float* qg = g_qbuf + ((0 * BDIM + b) * HEADS + h) * NTOK * HD;
    const float* kg = g_qbuf + ((1 * BDIM + b) * HEADS + h) * NTOK * HD;
    const float* vg = g_qbuf + ((2 * BDIM + b) * HEADS + h) * NTOK * HD;
    for (int idx = tid; idx < NTOK * HD; idx += 256) {
        int n = idx >> 5, d = idx & 31;
        qs[n * 33 + d] = qg[idx] * scale;
        ks[n * 33 + d] = kg[idx];
        vs[n * 33 + d] = vg[idx];
    }
    __syncthreads();
    for (int n = w; n < NTOK; n += 8) {
        float s[8];
#pragma unroll
        for (int u = 0; u < 8; u++) {
            int j = lane + 32 * u;
            float a = 0.f;
#pragma unroll 8
            for (int d = 0; d < HD; d++) a = fmaf(qs[n * 33 + d], ks[j * 33 + d], a);
            s[u] = a;
        }
        float mx = s[0];
#pragma unroll
        for (int u = 1; u < 8; u++) mx = fmaxf(mx, s[u]);
#pragma unroll
        for (int o = 16; o > 0; o >>= 1) mx = fmaxf(mx, __shfl_xor_sync(0xffffffffu, mx, o));
        float sum = 0.f;
#pragma unroll
        for (int u = 0; u < 8; u++) { s[u] = __expf(s[u] - mx); sum += s[u]; }
#pragma unroll
        for (int o = 16; o > 0; o >>= 1) sum += __shfl_xor_sync(0xffffffffu, sum, o);
        float inv = 1.f / sum;
#pragma unroll
        for (int u = 0; u < 8; u++) prob[w * 256 + lane + 32 * u] = s[u] * inv;
        __syncwarp();
        float acc = 0.f;
#pragma unroll 8
        for (int j = 0; j < NTOK; j++) acc = fmaf(prob[w * 256 + j], vs[j * 33 + lane], acc);
        g_attnout[(b * NTOK + n) * CDIM + h * HD + lane] = acc;
        __syncwarp();
    }
}

// ---------------------------------------------------------------------------
// K3: x1 = LN(x + attnout @ wo + bo) via tf32 mma. grid 128, 256 thr.
// ---------------------------------------------------------------------------
__global__ void __launch_bounds__(256, 1)
proj_mma_kernel(const float* __restrict__ x, const float* __restrict__ bo,
                const float* __restrict__ g1, const float* __restrict__ b1) {
    extern __shared__ __align__(16) float smF[];
    uint32_t sbase;
    asm("{ .reg .u64 t; cvta.to.shared.u64 t, %1; cvt.u32.u64 %0, t; }"
        : "=r"(sbase) : "l"((const void*)smF));
    int tid = threadIdx.x, warp = tid >> 5, lane = tid & 31;
    int r0 = blockIdx.x * 16;

    for (int idx = tid; idx < 16 * 256; idx += 256) {
        int r = idx >> 8, c = idx & 255;
        sts1u(sbase + astf(r, c), f2tf(g_attnout[(r0 + r) * 256 + c]));
    }
    prefB32(sbase + P_W0, g_wo_t, tid);

    float acc[4][4];
    run_gemm_tf(sbase, g_wo_t, acc, warp, lane, tid);

    float* red = smF + P_RED / 4;
    float* stt = smF + P_STAT / 4;
    int quad = lane >> 2, q = lane & 3;
    float v[4][4];
    float sl = 0.f, sh = 0.f, ql = 0.f, qh = 0.f;
#pragma unroll
    for (int t = 0; t < 4; t++) {
        int cb = warp * 32 + t * 8 + q * 2;
        float2 bias = *(const float2*)(bo + cb);
        float2 rlo = *(const float2*)(x + (r0 + quad) * 256 + cb);
        float2 rhi = *(const float2*)(x + (r0 + quad + 8) * 256 + cb);
        float v00 = acc[t][0] + bias.x + rlo.x, v01 = acc[t][1] + bias.y + rlo.y;
        float v10 = acc[t][2] + bias.x + rhi.x, v11 = acc[t][3] + bias.y + rhi.y;
        v[t][0] = v00; v[t][1] = v01; v[t][2] = v10; v[t][3] = v11;
        sl += v00 + v01; ql += v00 * v00 + v01 * v01;
        sh += v10 + v11; qh += v10 * v10 + v11 * v11;
    }
#pragma unroll
    for (int o = 1; o < 4; o <<= 1) {
        sl += __shfl_xor_sync(0xffffffffu, sl, o);
        sh += __shfl_xor_sync(0xffffffffu, sh, o);
        ql += __shfl_xor_sync(0xffffffffu, ql, o);
        qh += __shfl_xor_sync(0xffffffffu, qh, o);
    }
    if (q == 0) {
        red[warp * 16 + quad] = sl;
        red[warp * 16 + quad + 8] = sh;
        red[128 + warp * 16 + quad] = ql;
        red[128 + warp * 16 + quad + 8] = qh;
    }
    __syncthreads();
    if (tid < 16) {
        float ts = 0.f, tq = 0.f;
#pragma unroll
        for (int w = 0; w < 8; w++) { ts += red[w * 16 + tid]; tq += red[128 + w * 16 + tid]; }
        float mean = ts * (1.f / 256.f);
        float rstd = rsqrtf(tq * (1.f / 256.f) - mean * mean + EPSLN);
        stt[tid] = rstd; stt[16 + tid] = -mean * rstd;
    }
    __syncthreads();
    float Al = stt[quad], Bl = stt[16 + quad];
    float Ah = stt[quad + 8], Bh = stt[16 + quad + 8];
#pragma unroll
    for (int t = 0; t < 4; t++) {
        int cb = warp * 32 + t * 8 + q * 2;
        float2 gg = *(const float2*)(g1 + cb);
        float2 nn = *(const float2*)(b1 + cb);
        float2 olo, ohi;
        olo.x = (v[t][0] * Al + Bl) * gg.x + nn.x;
        olo.y = (v[t][1] * Al + Bl) * gg.y + nn.y;
        ohi.x = (v[t][2] * Ah + Bh) * gg.x + nn.x;
        ohi.y = (v[t][3] * Ah + Bh) * gg.y + nn.y;
        *(float2*)(g_x1 + (r0 + quad) * 256 + cb) = olo;
        *(float2*)(g_x1 + (r0 + quad + 8) * 256 + cb) = ohi;
    }
}

// ---------------------------------------------------------------------------
// ODE kernel (unchanged from R11): 128 CTAs x 256 threads, bf16 m16n8k16
// ---------------------------------------------------------------------------
__device__ __forceinline__ void prefB(uint32_t sdst, const uint32_t* gsrc, int tid) {
#pragma unroll
    for (int i = 0; i < 4; i++) {
        int off = (tid + i * 256) * 16;
        cp_async16(sdst + off, (const char*)gsrc + off);
    }
    cp_commit();
}

__device__ __forceinline__ void run_gemm(uint32_t sbase, int gemmIdx, float acc[4][4],
                                         int warp, int lane, int tid) {
    int quad = lane >> 2, q = lane & 3;
#pragma unroll
    for (int t = 0; t < 4; t++)
#pragma unroll
        for (int j = 0; j < 4; j++) acc[t][j] = 0.f;
    uint32_t aBase = sbase + OFF_AST + (uint32_t)(quad * 32 + q * 8);
    uint32_t bBase = (uint32_t)((warp * 32 + quad) * 32 + q * 8);
    for (int p = 0; p < 8; p++) {
        int blk = gemmIdx * 8 + p;
        int nb = (blk + 1) & 15;
        const uint32_t* src = (nb < 8) ? g_wt1 + nb * 4096 : g_wt2 + (nb - 8) * 4096;
        prefB(sbase + ((nb & 1) ? OFF_W1 : OFF_W0), src, tid);
        cp_wait1();
        __syncthreads();
        uint32_t wb = sbase + ((blk & 1) ? OFF_W1 : OFF_W0) + bBase;
#pragma unroll
        for (int cc = 0; cc < 2; cc++) {
            int c = p * 2 + cc;
            uint32_t a0, a1, a2, a3;
            lds2u(aBase + c * 512, a0, a2);
            lds2u(aBase + c * 512 + 256, a1, a3);
            uint32_t bb = wb + cc * 8192;
#pragma unroll
            for (int t = 0; t < 4; t++) {
                uint32_t b0, b1;
                lds2u(bb + t * 256, b0, b1);
                mma_bf(acc[t][0], acc[t][1], acc[t][2], acc[t][3], a0, a1, a2, a3, b0, b1);
            }
        }
    }
}

template <int ST>
__device__ __forceinline__ void epi2(float* smF, uint32_t sbase, float acc[4][4],
                                     int warp, int lane, int tid) {
    int quad = lane >> 2, q = lane & 3;
    float* RES = smF + ((ST == 0) ? OFF_YS : OFF_AR) / 4;
    float* CST = smF + OFF_CST / 4;
    float* red = smF + OFF_RED / 4;
    float* stt = smF + OFF_STAT / 4;
    float v[4][4];
    float sl = 0.f, sh = 0.f, ql = 0.f, qh = 0.f;
#pragma unroll
    for (int t = 0; t < 4; t++) {
        int cb = warp * 32 + t * 8 + q * 2;
        float2 bias = *(float2*)(CST + 256 + cb);
        float2 rlo = *(float2*)(RES + quad * RMJ + cb);
        float2 rhi = *(float2*)(RES + (quad + 8) * RMJ + cb);
        float v00 = acc[t][0] + bias.x + rlo.x, v01 = acc[t][1] + bias.y + rlo.y;
        float v10 = acc[t][2] + bias.x + rhi.x, v11 = acc[t][3] + bias.y + rhi.y;
        v[t][0] = v00; v[t][1] = v01; v[t][2] = v10; v[t][3] = v11;
        sl += v00 + v01; ql += v00 * v00 + v01 * v01;
        sh += v10 + v11; qh += v10 * v10 + v11 * v11;
    }
#pragma unroll
    for (int o = 1; o < 4; o <<= 1) {
        sl += __shfl_xor_sync(0xffffffffu, sl, o);
        sh += __shfl_xor_sync(0xffffffffu, sh, o);
        ql += __shfl_xor_sync(0xffffffffu, ql, o);
        qh += __shfl_xor_sync(0xffffffffu, qh, o);
    }
    if (q == 0) {
        red[warp * 16 + quad] = sl;
        red[warp * 16 + quad + 8] = sh;
        red[128 + warp * 16 + quad] = ql;
        red[128 + warp * 16 + quad + 8] = qh;
    }
    __syncthreads();
    if (tid < 16) {
        float ts = 0.f, tq = 0.f;
#pragma unroll
        for (int w = 0; w < 8; w++) { ts += red[w * 16 + tid]; tq += red[128 + w * 16 + tid]; }
        float mean = ts * (1.f / 256.f);
        float rstd = rsqrtf(tq * (1.f / 256.f) - mean * mean + EPSLN);
        stt[tid] = rstd; stt[16 + tid] = -mean * rstd;
    }
    __syncthreads();
    float Al = stt[quad], Bl = stt[16 + quad];
    float Ah = stt[quad + 8], Bh = stt[16 + quad + 8];
    float* Y  = smF + OFF_YS / 4;
    float* K1 = smF + OFF_K1 / 4;
    float* K2 = smF + OFF_K2 / 4;
    float* K3 = smF + OFF_K3 / 4;
    float* AR = smF + OFF_AR / 4;
#pragma unroll
    for (int t = 0; t < 4; t++) {
        int cb = warp * 32 + t * 8 + q * 2;
        int ol = quad * RMJ + cb, oh = (quad + 8) * RMJ + cb;
        float2 gg = *(float2*)(CST + 512 + cb);
        float2 nn = *(float2*)(CST + 768 + cb);
        float k00 = (v[t][0] * Al + Bl) * gg.x + nn.x;
        float k01 = (v[t][1] * Al + Bl) * gg.y + nn.y;
        float k10 = (v[t][2] * Ah + Bh) * gg.x + nn.x;
        float k11 = (v[t][3] * Ah + Bh) * gg.y + nn.y;
        float2 ylo = *(float2*)(Y + ol), yhi = *(float2*)(Y + oh);
        float a00, a01, a10, a11;
        if (ST == 0) {
            *(float2*)(K1 + ol) = make_float2(k00, k01);
            *(float2*)(K1 + oh) = make_float2(k10, k11);
            const float c3 = DT * (1.f / 3.f);
            a00 = ylo.x + c3 * k00; a01 = ylo.y + c3 * k01;
            a10 = yhi.x + c3 * k10; a11 = yhi.y + c3 * k11;
        } else if (ST == 1) {
            float2 k1l = *(float2*)(K1 + ol), k1h = *(float2*)(K1 + oh);
            *(float2*)(K2 + ol) = make_float2(k00, k01);
            *(float2*)(K2 + oh) = make_float2(k10, k11);
            a00 = ylo.x + DT * (k00 - (1.f / 3.f) * k1l.x);
            a01 = ylo.y + DT * (k01 - (1.f / 3.f) * k1l.y);
            a10 = yhi.x + DT * (k10 - (1.f / 3.f) * k1h.x);
            a11 = yhi.y + DT * (k11 - (1.f / 3.f) * k1h.y);
        } else if (ST == 2) {
            float2 k1l = *(float2*)(K1 + ol), k1h = *(float2*)(K1 + oh);
            float2 k2l = *(float2*)(K2 + ol), k2h = *(float2*)(K2 + oh);
            *(float2*)(K3 + ol) = make_float2(k00, k01);
            *(float2*)(K3 + oh) = make_float2(k10, k11);
            a00 = ylo.x + DT * (k1l.x - k2l.x + k00);
            a01 = ylo.y + DT * (k1l.y - k2l.y + k01);
            a10 = yhi.x + DT * (k1h.x - k2h.x + k10);
            a11 = yhi.y + DT * (k1h.y - k2h.y + k11);
        } else {
            float2 k1l = *(float2*)(K1 + ol), k1h = *(float2*)(K1 + oh);
            float2 k2l = *(float2*)(K2 + ol), k2h = *(float2*)(K2 + oh);
            float2 k3l = *(float2*)(K3 + ol), k3h = *(float2*)(K3 + oh);
            a00 = ylo.x + (DT * 0.125f) * (k1l.x + 3.f * (k2l.x + k3l.x) + k00);
            a01 = ylo.y + (DT * 0.125f) * (k1l.y + 3.f * (k2l.y + k3l.y) + k01);
            a10 = yhi.x + (DT * 0.125f) * (k1h.x + 3.f * (k2h.x + k3h.x) + k10);
            a11 = yhi.y + (DT * 0.125f) * (k1h.y + 3.f * (k2h.y + k3h.y) + k11);
        }
        if (ST < 3) {
            *(float2*)(AR + ol) = make_float2(a00, a01);
            *(float2*)(AR + oh) = make_float2(a10, a11);
        } else {
            *(float2*)(Y + ol) = make_float2(a00, a01);
            *(float2*)(Y + oh) = make_float2(a10, a11);
        }
        sts1u(sbase + astb2(quad, cb), f2bf2(a00, a01));
        sts1u(sbase + astb2(quad + 8, cb), f2bf2(a10, a11));
    }
}

__global__ void __launch_bounds__(256, 1)
ode_mma_kernel(const int* __restrict__ lead, const int* __restrict__ nsp,
               const float* __restrict__ bl1, const float* __restrict__ bl2,
               const float* __restrict__ gn, const float* __restrict__ bn) {
    extern __shared__ __align__(16) float smF[];
    uint32_t sbase;
    asm("{ .reg .u64 t; cvta.to.shared.u64 t, %1; cvt.u32.u64 %0, t; }"
        : "=r"(sbase) : "l"((const void*)smF));
    int tid = threadIdx.x, warp = tid >> 5, lane = tid & 31;
    int r0 = blockIdx.x * 16;
    int steps = lead[r0 >> 8];
    int ns = nsp ? nsp[0] : 50;
    if (steps > ns) steps = ns;
    if (steps < 0) steps = 0;

    float* CST = smF + OFF_CST / 4;
    for (int i = tid; i < 256; i += 256) {
        CST[i] = bl1[i]; CST[256 + i] = bl2[i];
        CST[512 + i] = gn[i]; CST[768 + i] = bn[i];
    }
    for (int idx = tid; idx < 16 * 128; idx += 256) {
        int r = idx >> 7, kp = idx & 127;
        int cb = kp * 2;
        float2 vv = *(const float2*)(g_x1 + (r0 + r) * 256 + cb);
        smF[OFF_YS / 4 + r * RMJ + cb] = vv.x;
        smF[OFF_YS / 4 + r * RMJ + cb + 1] = vv.y;
        sts1u(sbase + astb2(r, cb), f2bf2(vv.x, vv.y));
    }
    __syncthreads();

    prefB(sbase + OFF_W0, g_wt1, tid);

    float acc[4][4];
    for (int s = 0; s < steps; s++) {
#pragma unroll 1
        for (int st = 0; st < 4; st++) {
            run_gemm(sbase, 0, acc, warp, lane, tid);
            __syncthreads();
            {
                int quad = lane >> 2, q = lane & 3;
#pragma unroll
                for (int t = 0; t < 4; t++) {
                    int cb = warp * 32 + t * 8 + q * 2;
                    float2 bias = *(float2*)(CST + cb);
                    sts1u(sbase + astb2(quad, cb),
                          f2bf2(fmaxf(acc[t][0] + bias.x, 0.f), fmaxf(acc[t][1] + bias.y, 0.f)));
                    sts1u(sbase + astb2(quad + 8, cb),
                          f2bf2(fmaxf(acc[t][2] + bias.x, 0.f), fmaxf(acc[t][3] + bias.y, 0.f)));
                }
            }
            run_gemm(sbase, 1, acc, warp, lane, tid);
            if (st == 0)      epi2<0>(smF, sbase, acc, warp, lane, tid);
            else if (st == 1) epi2<1>(smF, sbase, acc, warp, lane, tid);
            else if (st == 2) epi2<2>(smF, sbase, acc, warp, lane, tid);
            else              epi2<3>(smF, sbase, acc, warp, lane, tid);
            __syncthreads();
        }
    }
    cp_wait0();
    __syncthreads();
    for (int idx = tid; idx < 16 * 256; idx += 256) {
        int r = idx >> 8, c = idx & 255;
        g_ode[(r0 + r) * 256 + c] = smF[OFF_YS / 4 + r * RMJ + c];
    }
}

// ---------------------------------------------------------------------------
// K5: out = LN(x1 + ode; g2,b2)
// ---------------------------------------------------------------------------
__global__ void final_ln_kernel(const float* __restrict__ g2, const float* __restrict__ b2,
                                float* __restrict__ out) {
    int tid = threadIdx.x, lane = tid & 31, w = tid >> 5;
    int r = blockIdx.x * 8 + w;
    float v[8], ls = 0.f, lq = 0.f;
#pragma unroll
    for (int u = 0; u < 8; u++) {
        int c = lane + 32 * u;
        float t = g_x1[r * CDIM + c] + g_ode[r * CDIM + c];
        v[u] = t; ls += t; lq += t * t;
    }
#pragma unroll
    for (int o = 16; o > 0; o >>= 1) {
        ls += __shfl_xor_sync(0xffffffffu, ls, o);
        lq += __shfl_xor_sync(0xffffffffu, lq, o);
    }
    float mean = ls * (1.f / 256.f);
    float rstd = rsqrtf(lq * (1.f / 256.f) - mean * mean + EPSLN);
#pragma unroll
    for (int u = 0; u < 8; u++) {
        int c = lane + 32 * u;
        out[r * CDIM + c] = (v[u] - mean) * rstd * g2[c] + b2[c];
    }
}

// ---------------------------------------------------------------------------
// Launch
// ---------------------------------------------------------------------------
extern "C" void kernel_launch(void* const* d_in, const int* in_sizes, int n_in,
                              void* d_out, int out_size) {
    const float* x    = (const float*)d_in[0];
    const float* wqkv = (const float*)d_in[1];
    const float* bqkv = (const float*)d_in[2];
    const float* wo   = (const float*)d_in[3];
    const float* bo   = (const float*)d_in[4];
    const float* g1   = (const float*)d_in[5];
    const float* b1   = (const float*)d_in[6];
    const float* g2   = (const float*)d_in[7];
    const float* b2   = (const float*)d_in[8];
    const float* wl1  = (const float*)d_in[9];
    const float* bl1  = (const float*)d_in[10];
    const float* wl2  = (const float*)d_in[11];
    const float* bl2  = (const float*)d_in[12];
    const float* gn   = (const float*)d_in[13];
    const float* bn   = (const float*)d_in[14];
    const int* lead   = (const int*)d_in[15];
    const int* nsteps = (n_in > 16) ? (const int*)d_in[16] : nullptr;
    float* out = (float*)d_out;

    cudaFuncSetAttribute(attn_kernel, cudaFuncAttributeMaxDynamicSharedMemorySize, ATTN_SMEM);
    cudaFuncSetAttribute(ode_mma_kernel, cudaFuncAttributeMaxDynamicSharedMemorySize, ODE_SMEM);
    cudaFuncSetAttribute(qkv_mma_kernel, cudaFuncAttributeMaxDynamicSharedMemorySize, QKV_SMEM);
    cudaFuncSetAttribute(proj_mma_kernel, cudaFuncAttributeMaxDynamicSharedMemorySize, PROJ_SMEM);

    prep_w_kernel<<<128, 256>>>(wl1, wl2);
    prep_qkv_kernel<<<dim3(256, 3), 256>>>(wqkv);
    prep_wo_kernel<<<256, 256>>>(wo);
    qkv_mma_kernel<<<dim3(128, 3), 256, QKV_SMEM>>>(x, bqkv);
    attn_kernel<<<64, 256, ATTN_SMEM>>>();
    proj_mma_kernel<<<128, 256, PROJ_SMEM>>>(x, bo, g1, b1);
    ode_mma_kernel<<<128, 256, ODE_SMEM>>>(lead, nsteps, bl1, bl2, gn, bn);
    final_ln_kernel<<<256, 256>>>(g2, b2, out);
}

// round 13
// speedup vs baseline: 4.7094x; 1.0748x over previous
#include <cuda_runtime.h>
#include <math.h>
#include <stdint.h>

#define EPSLN 1e-5f
#define DT    0.01f
#define CDIM  256
#define BDIM  8
#define NTOK  256
#define HEADS 8
#define HD    32
#define ROWS  (BDIM * NTOK)

#define RMJ   264   // row-major state stride (floats)

// ---- ODE smem layout (bytes) ----
#define OFF_YS   0          // 16896
#define OFF_AR   16896      // 16896
#define OFF_AST  33792      // 8192 (bf16 A-stage)
#define OFF_W1R  41984      // 131072 (W1 resident, bf16 MMA-B layout)
#define OFF_W20  173056     // 16384
#define OFF_W21  189440     // 16384
#define OFF_W22  205824     // 16384
#define OFF_RED  222208     // 1024
#define OFF_STAT 223232     // 128
#define OFF_CST  223360     // 4096
#define ODE_SMEM 227456

// ---- prologue mma kernels smem layout (bytes) ----
#define P_AST    0          // 16 KB tf32 A-stage
#define P_W0     16384      // 32 KB
#define P_W1     49152      // 32 KB
#define P_RED    81920      // 256 floats
#define P_STAT   82944      // 32 floats
#define QKV_SMEM 81920
#define PROJ_SMEM 83072

// ---------------------------------------------------------------------------
// Scratch globals
// ---------------------------------------------------------------------------
__device__ float g_qbuf[3 * BDIM * HEADS * NTOK * HD];
__device__ float g_attnout[ROWS * CDIM];
__device__ float g_x1[ROWS * CDIM];
__device__ float g_ode[ROWS * CDIM];
__device__ float g_k1[ROWS * CDIM];
__device__ float g_k2[ROWS * CDIM];
__device__ float g_k3[ROWS * CDIM];
// bf16-pair ODE weights in MMA-B layout
__device__ uint32_t g_wt1[CDIM * CDIM / 2];
__device__ uint32_t g_wt2[CDIM * CDIM / 2];
// tf32 MMA-B layout prologue weights
__device__ float g_wqkv_t[CDIM * 768];
__device__ float g_wo_t[CDIM * CDIM];

// ---------------------------------------------------------------------------
// helpers
// ---------------------------------------------------------------------------
__device__ __forceinline__ uint32_t f2bf2(float lo, float hi) {
    uint32_t r; asm("cvt.rn.bf16x2.f32 %0, %1, %2;" : "=r"(r) : "f"(hi), "f"(lo)); return r;
}
__device__ __forceinline__ uint32_t f2tf(float f) {
    uint32_t r; asm("cvt.rna.tf32.f32 %0, %1;" : "=r"(r) : "f"(f)); return r;
}
__device__ __forceinline__ void lds2u(uint32_t a, uint32_t& x, uint32_t& y) {
    asm volatile("ld.shared.v2.b32 {%0,%1}, [%2];" : "=r"(x), "=r"(y) : "r"(a));
}
__device__ __forceinline__ void sts1u(uint32_t a, uint32_t v) {
    asm volatile("st.shared.b32 [%0], %1;" :: "r"(a), "r"(v));
}
__device__ __forceinline__ void cp_async16(uint32_t sdst, const void* gsrc) {
    asm volatile("cp.async.cg.shared.global [%0], [%1], 16;" :: "r"(sdst), "l"(gsrc));
}
__device__ __forceinline__ void cp_commit() { asm volatile("cp.async.commit_group;"); }
__device__ __forceinline__ void cp_wait1() { asm volatile("cp.async.wait_group 1;" ::: "memory"); }
__device__ __forceinline__ void cp_wait0() { asm volatile("cp.async.wait_group 0;" ::: "memory"); }

__device__ __forceinline__ void mma_bf(float& c0, float& c1, float& c2, float& c3,
                                       uint32_t a0, uint32_t a1, uint32_t a2, uint32_t a3,
                                       uint32_t b0, uint32_t b1) {
    asm volatile(
        "mma.sync.aligned.m16n8k16.row.col.f32.bf16.bf16.f32 "
        "{%0,%1,%2,%3},{%4,%5,%6,%7},{%8,%9},{%0,%1,%2,%3};"
        : "+f"(c0), "+f"(c1), "+f"(c2), "+f"(c3)
        : "r"(a0), "r"(a1), "r"(a2), "r"(a3), "r"(b0), "r"(b1));
}
__device__ __forceinline__ void mma_tf(float& c0, float& c1, float& c2, float& c3,
                                       uint32_t a0, uint32_t a1, uint32_t a2, uint32_t a3,
                                       uint32_t b0, uint32_t b1) {
    asm volatile(
        "mma.sync.aligned.m16n8k8.row.col.f32.tf32.tf32.f32 "
        "{%0,%1,%2,%3},{%4,%5,%6,%7},{%8,%9},{%0,%1,%2,%3};"
        : "+f"(c0), "+f"(c1), "+f"(c2), "+f"(c3)
        : "r"(a0), "r"(a1), "r"(a2), "r"(a3), "r"(b0), "r"(b1));
}

// bf16 A-stage byte offset (ODE)
__device__ __forceinline__ uint32_t astb2(int r, int cb) {
    int pc = (cb >> 1) & 7;
    return OFF_AST + (uint32_t)((cb >> 4) * 512 + r * 32 + ((pc & 3) * 2 + (pc >> 2)) * 4);
}
// tf32 A-stage byte offset (prologue)
__device__ __forceinline__ uint32_t astf(int r, int c) {
    return P_AST + (uint32_t)((c >> 3) * 512 + r * 32 + (c & 3) * 8 + ((c >> 2) & 1) * 4);
}

// ---------------------------------------------------------------------------
// prep kernels
// ---------------------------------------------------------------------------
__global__ void prep_w_kernel(const float* __restrict__ wl1, const float* __restrict__ wl2) {
    int idx = blockIdx.x * 256 + threadIdx.x;
    int kp = idx >> 8, n = idx & 255;
    int k = kp * 2;
    int pc = kp & 7;
    int dst = (k >> 5) * 4096 + ((k >> 4) & 1) * 2048 + n * 8 + (pc & 3) * 2 + (pc >> 2);
    g_wt1[dst] = f2bf2(wl1[k * 256 + n], wl1[(k + 1) * 256 + n]);
    g_wt2[dst] = f2bf2(wl2[k * 256 + n], wl2[(k + 1) * 256 + n]);
}
__global__ void prep_qkv_kernel(const float* __restrict__ wqkv) {
    int k = blockIdx.x, n = threadIdx.x, g = blockIdx.y;
    int dst = g * 65536 + (k >> 5) * 8192 + ((k >> 3) & 3) * 2048 + n * 8 + (k & 3) * 2 + ((k >> 2) & 1);
    g_wqkv_t[dst] = __uint_as_float(f2tf(wqkv[k * 768 + g * 256 + n]));
}
__global__ void prep_wo_kernel(const float* __restrict__ wo) {
    int k = blockIdx.x, n = threadIdx.x;
    int dst = (k >> 5) * 8192 + ((k >> 3) & 3) * 2048 + n * 8 + (k & 3) * 2 + ((k >> 2) & 1);
    g_wo_t[dst] = __uint_as_float(f2tf(wo[k * 256 + n]));
}

// ---------------------------------------------------------------------------
// prologue tf32 GEMM core
// ---------------------------------------------------------------------------
__device__ __forceinline__ void prefB32(uint32_t sdst, const float* gsrc, int tid) {
#pragma unroll
    for (int i = 0; i < 8; i++) {
        int off = (tid + i * 256) * 16;
        cp_async16(sdst + off, (const char*)gsrc + off);
    }
    cp_commit();
}

__device__ __forceinline__ void run_gemm_tf(uint32_t sbase, const float* gw,
                                            float acc[4][4], int warp, int lane, int tid) {
    int quad = lane >> 2, q = lane & 3;
#pragma unroll
    for (int t = 0; t < 4; t++)
#pragma unroll
        for (int j = 0; j < 4; j++) acc[t][j] = 0.f;
    uint32_t aBase = sbase + P_AST + (uint32_t)(quad * 32 + q * 8);
    uint32_t bBase = (uint32_t)(warp * 1024 + quad * 32 + q * 8);
    for (int p = 0; p < 8; p++) {
        if (p < 7) {
            prefB32(sbase + (((p + 1) & 1) ? P_W1 : P_W0), gw + (p + 1) * 8192, tid);
            cp_wait1();
        } else {
            cp_wait0();
        }
        __syncthreads();
        uint32_t wb = sbase + ((p & 1) ? P_W1 : P_W0) + bBase;
#pragma unroll
        for (int kc4 = 0; kc4 < 4; kc4++) {
            int kcg = p * 4 + kc4;
            uint32_t a0, a1, a2, a3;
            lds2u(aBase + kcg * 512, a0, a2);
            lds2u(aBase + kcg * 512 + 256, a1, a3);
            uint32_t bb = wb + kc4 * 8192;
#pragma unroll
            for (int t = 0; t < 4; t++) {
                uint32_t b0, b1;
                lds2u(bb + t * 256, b0, b1);
                mma_tf(acc[t][0], acc[t][1], acc[t][2], acc[t][3], a0, a1, a2, a3, b0, b1);
            }
        }
    }
}

// ---------------------------------------------------------------------------
// K1: qkv via tf32 mma
// ---------------------------------------------------------------------------
__global__ void __launch_bounds__(256, 1)
qkv_mma_kernel(const float* __restrict__ x, const float* __restrict__ bqkv) {
    extern __shared__ __align__(16) float smF[];
    uint32_t sbase;
    asm("{ .reg .u64 t; cvta.to.shared.u64 t, %1; cvt.u32.u64 %0, t; }"
        : "=r"(sbase) : "l"((const void*)smF));
    int tid = threadIdx.x, warp = tid >> 5, lane = tid & 31;
    int r0 = blockIdx.x * 16, g = blockIdx.y;

    for (int idx = tid; idx < 16 * 256; idx += 256) {
        int r = idx >> 8, c = idx & 255;
        sts1u(sbase + astf(r, c), f2tf(x[(r0 + r) * 256 + c]));
    }
    prefB32(sbase + P_W0, g_wqkv_t + g * 65536, tid);

    float acc[4][4];
    run_gemm_tf(sbase, g_wqkv_t + g * 65536, acc, warp, lane, tid);

    int quad = lane >> 2, q = lane & 3;
#pragma unroll
    for (int t = 0; t < 4; t++) {
        int cb = warp * 32 + t * 8 + q * 2;
        float2 bias = *(const float2*)(bqkv + g * 256 + cb);
        int h = cb >> 5, d = cb & 31;
#pragma unroll
        for (int half = 0; half < 2; half++) {
            int r = r0 + quad + half * 8;
            int b = r >> 8, n = r & 255;
            float2 ov;
            ov.x = acc[t][2 * half + 0] + bias.x;
            ov.y = acc[t][2 * half + 1] + bias.y;
            *(float2*)(g_qbuf + (((g * BDIM + b) * HEADS + h) * NTOK + n) * HD + d) = ov;
        }
    }
}

// ---------------------------------------------------------------------------
// K2: attention — split over query halves (128 CTAs)
// ---------------------------------------------------------------------------
#define ATTN_SMEM ((3 * 256 * 33 + 8 * 256) * 4)
__global__ void attn_kernel() {
    extern __shared__ float sm[];
    float* qs = sm;
    float* ks = qs + 256 * 33;
    float* vs = ks + 256 * 33;
    float* prob = vs + 256 * 33;
    int tid = threadIdx.x, lane = tid & 31, w = tid >> 5;
    int bh = blockIdx.x >> 1, half = blockIdx.x & 1;
    int b = bh >> 3, h = bh & 7;
    const float scale = 0.17677669529663687f;
    const float* qg = g_qbuf + ((0 * BDIM + b) * HEADS + h) * NTOK * HD;
    const float* kg = g_qbuf + ((1 * BDIM + b) * HEADS + h) * NTOK * HD;
    const float* vg = g_qbuf + ((2 * BDIM + b) * HEADS + h) * NTOK * HD;
    for (int idx = tid; idx < NTOK * HD; idx += 256) {
        int n = idx >> 5, d = idx & 31;
        qs[n * 33 + d] = qg[idx] * scale;
        ks[n * 33 + d] = kg[idx];
        vs[n * 33 + d] = vg[idx];
    }
    __syncthreads();
    for (int n = 128 * half + w; n < 128 * (half + 1); n += 8) {
        float s[8];
#pragma unroll
        for (int u = 0; u < 8; u++) {
            int j = lane + 32 * u;
            float a = 0.f;
#pragma unroll 8
            for (int d = 0; d < HD; d++) a = fmaf(qs[n * 33 + d], ks[j * 33 + d], a);
            s[u] = a;
        }
        float mx = s[0];
#pragma unroll
        for (int u = 1; u < 8; u++) mx = fmaxf(mx, s[u]);
#pragma unroll
        for (int o = 16; o > 0; o >>= 1) mx = fmaxf(mx, __shfl_xor_sync(0xffffffffu, mx, o));
        float sum = 0.f;
#pragma unroll
        for (int u = 0; u < 8; u++) { s[u] = __expf(s[u] - mx); sum += s[u]; }
#pragma unroll
        for (int o = 16; o > 0; o >>= 1) sum += __shfl_xor_sync(0xffffffffu, sum, o);
        float inv = 1.f / sum;
#pragma unroll
        for (int u = 0; u < 8; u++) prob[w * 256 + lane + 32 * u] = s[u] * inv;
        __syncwarp();
        float acc = 0.f;
#pragma unroll 8
        for (int j = 0; j < NTOK; j++) acc = fmaf(prob[w * 256 + j], vs[j * 33 + lane], acc);
        g_attnout[(b * NTOK + n) * CDIM + h * HD + lane] = acc;
        __syncwarp();
    }
}

// ---------------------------------------------------------------------------
// K3: x1 = LN(x + attnout @ wo + bo) via tf32 mma
// ---------------------------------------------------------------------------
__global__ void __launch_bounds__(256, 1)
proj_mma_kernel(const float* __restrict__ x, const float* __restrict__ bo,
                const float* __restrict__ g1, const float* __restrict__ b1) {
    extern __shared__ __align__(16) float smF[];
    uint32_t sbase;
    asm("{ .reg .u64 t; cvta.to.shared.u64 t, %1; cvt.u32.u64 %0, t; }"
        : "=r"(sbase) : "l"((const void*)smF));
    int tid = threadIdx.x, warp = tid >> 5, lane = tid & 31;
    int r0 = blockIdx.x * 16;

    for (int idx = tid; idx < 16 * 256; idx += 256) {
        int r = idx >> 8, c = idx & 255;
        sts1u(sbase + astf(r, c), f2tf(g_attnout[(r0 + r) * 256 + c]));
    }
    prefB32(sbase + P_W0, g_wo_t, tid);

    float acc[4][4];
    run_gemm_tf(sbase, g_wo_t, acc, warp, lane, tid);

    float* red = smF + P_RED / 4;
    float* stt = smF + P_STAT / 4;
    int quad = lane >> 2, q = lane & 3;
    float v[4][4];
    float sl = 0.f, sh = 0.f, ql = 0.f, qh = 0.f;
#pragma unroll
    for (int t = 0; t < 4; t++) {
        int cb = warp * 32 + t * 8 + q * 2;
        float2 bias = *(const float2*)(bo + cb);
        float2 rlo = *(const float2*)(x + (r0 + quad) * 256 + cb);
        float2 rhi = *(const float2*)(x + (r0 + quad + 8) * 256 + cb);
        float v00 = acc[t][0] + bias.x + rlo.x, v01 = acc[t][1] + bias.y + rlo.y;
        float v10 = acc[t][2] + bias.x + rhi.x, v11 = acc[t][3] + bias.y + rhi.y;
        v[t][0] = v00; v[t][1] = v01; v[t][2] = v10; v[t][3] = v11;
        sl += v00 + v01; ql += v00 * v00 + v01 * v01;
        sh += v10 + v11; qh += v10 * v10 + v11 * v11;
    }
#pragma unroll
    for (int o = 1; o < 4; o <<= 1) {
        sl += __shfl_xor_sync(0xffffffffu, sl, o);
        sh += __shfl_xor_sync(0xffffffffu, sh, o);
        ql += __shfl_xor_sync(0xffffffffu, ql, o);
        qh += __shfl_xor_sync(0xffffffffu, qh, o);
    }
    if (q == 0) {
        red[warp * 16 + quad] = sl;
        red[warp * 16 + quad + 8] = sh;
        red[128 + warp * 16 + quad] = ql;
        red[128 + warp * 16 + quad + 8] = qh;
    }
    __syncthreads();
    if (tid < 16) {
        float ts = 0.f, tq = 0.f;
#pragma unroll
        for (int w = 0; w < 8; w++) { ts += red[w * 16 + tid]; tq += red[128 + w * 16 + tid]; }
        float mean = ts * (1.f / 256.f);
        float rstd = rsqrtf(tq * (1.f / 256.f) - mean * mean + EPSLN);
        stt[tid] = rstd; stt[16 + tid] = -mean * rstd;
    }
    __syncthreads();
    float Al = stt[quad], Bl = stt[16 + quad];
    float Ah = stt[quad + 8], Bh = stt[16 + quad + 8];
#pragma unroll
    for (int t = 0; t < 4; t++) {
        int cb = warp * 32 + t * 8 + q * 2;
        float2 gg = *(const float2*)(g1 + cb);
        float2 nn = *(const float2*)(b1 + cb);
        float2 olo, ohi;
        olo.x = (v[t][0] * Al + Bl) * gg.x + nn.x;
        olo.y = (v[t][1] * Al + Bl) * gg.y + nn.y;
        ohi.x = (v[t][2] * Ah + Bh) * gg.x + nn.x;
        ohi.y = (v[t][3] * Ah + Bh) * gg.y + nn.y;
        *(float2*)(g_x1 + (r0 + quad) * 256 + cb) = olo;
        *(float2*)(g_x1 + (r0 + quad + 8) * 256 + cb) = ohi;
    }
}

// ---------------------------------------------------------------------------
// ODE kernel: W1 resident in smem; W2 streamed via 3-buffer ring; k1-3 global.
// ---------------------------------------------------------------------------
__device__ __forceinline__ void prefB(uint32_t sdst, const uint32_t* gsrc, int tid) {
#pragma unroll
    for (int i = 0; i < 4; i++) {
        int off = (tid + i * 256) * 16;
        cp_async16(sdst + off, (const char*)gsrc + off);
    }
    cp_commit();
}

// GEMM1: W1 resident — no waits, no barriers
__device__ __forceinline__ void run_gemm1(uint32_t sbase, float acc[4][4], int warp, int lane) {
    int quad = lane >> 2, q = lane & 3;
#pragma unroll
    for (int t = 0; t < 4; t++)
#pragma unroll
        for (int j = 0; j < 4; j++) acc[t][j] = 0.f;
    uint32_t aBase = sbase + OFF_AST + (uint32_t)(quad * 32 + q * 8);
    uint32_t bBase = (uint32_t)((warp * 32 + quad) * 32 + q * 8);
#pragma unroll 2
    for (int p = 0; p < 8; p++) {
        uint32_t wb = sbase + OFF_W1R + p * 16384 + bBase;
#pragma unroll
        for (int cc = 0; cc < 2; cc++) {
            int c = p * 2 + cc;
            uint32_t a0, a1, a2, a3;
            lds2u(aBase + c * 512, a0, a2);
            lds2u(aBase + c * 512 + 256, a1, a3);
            uint32_t bb = wb + cc * 8192;
#pragma unroll
            for (int t = 0; t < 4; t++) {
                uint32_t b0, b1;
                lds2u(bb + t * 256, b0, b1);
                mma_bf(acc[t][0], acc[t][1], acc[t][2], acc[t][3], a0, a1, a2, a3, b0, b1);
            }
        }
    }
}

// GEMM2: W2 streamed, 3-buffer ring (prefetch after barrier: race-free)
__device__ __forceinline__ void run_gemm2(uint32_t sbase, float acc[4][4],
                                          int warp, int lane, int tid) {
    int quad = lane >> 2, q = lane & 3;
#pragma unroll
    for (int t = 0; t < 4; t++)
#pragma unroll
        for (int j = 0; j < 4; j++) acc[t][j] = 0.f;
    uint32_t aBase = sbase + OFF_AST + (uint32_t)(quad * 32 + q * 8);
    uint32_t bBase = (uint32_t)((warp * 32 + quad) * 32 + q * 8);
    const uint32_t W2B[3] = { OFF_W20, OFF_W21, OFF_W22 };
    for (int p = 0; p < 8; p++) {
        if (p < 7) cp_wait1(); else cp_wait0();
        __syncthreads();
        if (p < 6) {
            int nb = p + 2;
            int bi = nb - (nb >= 3 ? 3 : 0); if (bi >= 3) bi -= 3;
            prefB(sbase + W2B[nb % 3], g_wt2 + nb * 4096, tid);
        }
        uint32_t wb = sbase + W2B[p % 3] + bBase;
#pragma unroll
        for (int cc = 0; cc < 2; cc++) {
            int c = p * 2 + cc;
            uint32_t a0, a1, a2, a3;
            lds2u(aBase + c * 512, a0, a2);
            lds2u(aBase + c * 512 + 256, a1, a3);
            uint32_t bb = wb + cc * 8192;
#pragma unroll
            for (int t = 0; t < 4; t++) {
                uint32_t b0, b1;
                lds2u(bb + t * 256, b0, b1);
                mma_bf(acc[t][0], acc[t][1], acc[t][2], acc[t][3], a0, a1, a2, a3, b0, b1);
            }
        }
    }
}

template <int ST>
__device__ __forceinline__ void epi2(float* smF, uint32_t sbase, float acc[4][4],
                                     int warp, int lane, int tid, int r0) {
    int quad = lane >> 2, q = lane & 3;
    float* RES = smF + ((ST == 0) ? OFF_YS : OFF_AR) / 4;
    float* CST = smF + OFF_CST / 4;
    float* red = smF + OFF_RED / 4;
    float* stt = smF + OFF_STAT / 4;
    float v[4][4];
    float sl = 0.f, sh = 0.f, ql = 0.f, qh = 0.f;
#pragma unroll
    for (int t = 0; t < 4; t++) {
        int cb = warp * 32 + t * 8 + q * 2;
        float2 bias = *(float2*)(CST + 256 + cb);
        float2 rlo = *(float2*)(RES + quad * RMJ + cb);
        float2 rhi = *(float2*)(RES + (quad + 8) * RMJ + cb);
        float v00 = acc[t][0] + bias.x + rlo.x, v01 = acc[t][1] + bias.y + rlo.y;
        float v10 = acc[t][2] + bias.x + rhi.x, v11 = acc[t][3] + bias.y + rhi.y;
        v[t][0] = v00; v[t][1] = v01; v[t][2] = v10; v[t][3] = v11;
        sl += v00 + v01; ql += v00 * v00 + v01 * v01;
        sh += v10 + v11; qh += v10 * v10 + v11 * v11;
    }
#pragma unroll
    for (int o = 1; o < 4; o <<= 1) {
        sl += __shfl_xor_sync(0xffffffffu, sl, o);
        sh += __shfl_xor_sync(0xffffffffu, sh, o);
        ql += __shfl_xor_sync(0xffffffffu, ql, o);
        qh += __shfl_xor_sync(0xffffffffu, qh, o);
    }
    if (q == 0) {
        red[warp * 16 + quad] = sl;
        red[warp * 16 + quad + 8] = sh;
        red[128 + warp * 16 + quad] = ql;
        red[128 + warp * 16 + quad + 8] = qh;
    }
    __syncthreads();
    if (tid < 16) {
        float ts = 0.f, tq = 0.f;
#pragma unroll
        for (int w = 0; w < 8; w++) { ts += red[w * 16 + tid]; tq += red[128 + w * 16 + tid]; }
        float mean = ts * (1.f / 256.f);
        float rstd = rsqrtf(tq * (1.f / 256.f) - mean * mean + EPSLN);
        stt[tid] = rstd; stt[16 + tid] = -mean * rstd;
    }
    __syncthreads();
    float Al = stt[quad], Bl = stt[16 + quad];
    float Ah = stt[quad + 8], Bh = stt[16 + quad + 8];
    float* Y  = smF + OFF_YS / 4;
    float* AR = smF + OFF_AR / 4;
#pragma unroll
    for (int t = 0; t < 4; t++) {
        int cb = warp * 32 + t * 8 + q * 2;
        int ol = quad * RMJ + cb, oh = (quad + 8) * RMJ + cb;
        int gl = (r0 + quad) * 256 + cb, gh = (r0 + quad + 8) * 256 + cb;
        float2 gg = *(float2*)(CST + 512 + cb);
        float2 nn = *(float2*)(CST + 768 + cb);
        float k00 = (v[t][0] * Al + Bl) * gg.x + nn.x;
        float k01 = (v[t][1] * Al + Bl) * gg.y + nn.y;
        float k10 = (v[t][2] * Ah + Bh) * gg.x + nn.x;
        float k11 = (v[t][3] * Ah + Bh) * gg.y + nn.y;
        float2 ylo = *(float2*)(Y + ol), yhi = *(float2*)(Y + oh);
        float a00, a01, a10, a11;
        if (ST == 0) {
            *(float2*)(g_k1 + gl) = make_float2(k00, k01);
            *(float2*)(g_k1 + gh) = make_float2(k10, k11);
            const float c3 = DT * (1.f / 3.f);
            a00 = ylo.x + c3 * k00; a01 = ylo.y + c3 * k01;
            a10 = yhi.x + c3 * k10; a11 = yhi.y + c3 * k11;
        } else if (ST == 1) {
            float2 k1l = *(const float2*)(g_k1 + gl), k1h = *(const float2*)(g_k1 + gh);
            *(float2*)(g_k2 + gl) = make_float2(k00, k01);
            *(float2*)(g_k2 + gh) = make_float2(k10, k11);
            a00 = ylo.x + DT * (k00 - (1.f / 3.f) * k1l.x);
            a01 = ylo.y + DT * (k01 - (1.f / 3.f) * k1l.y);
            a10 = yhi.x + DT * (k10 - (1.f / 3.f) * k1h.x);
            a11 = yhi.y + DT * (k11 - (1.f / 3.f) * k1h.y);
        } else if (ST == 2) {
            float2 k1l = *(const float2*)(g_k1 + gl), k1h = *(const float2*)(g_k1 + gh);
            float2 k2l = *(const float2*)(g_k2 + gl), k2h = *(const float2*)(g_k2 + gh);
            *(float2*)(g_k3 + gl) = make_float2(k00, k01);
            *(float2*)(g_k3 + gh) = make_float2(k10, k11);
            a00 = ylo.x + DT * (k1l.x - k2l.x + k00);
            a01 = ylo.y + DT * (k1l.y - k2l.y + k01);
            a10 = yhi.x + DT * (k1h.x - k2h.x + k10);
            a11 = yhi.y + DT * (k1h.y - k2h.y + k11);
        } else {
            float2 k1l = *(const float2*)(g_k1 + gl), k1h = *(const float2*)(g_k1 + gh);
            float2 k2l = *(const float2*)(g_k2 + gl), k2h = *(const float2*)(g_k2 + gh);
            float2 k3l = *(const float2*)(g_k3 + gl), k3h = *(const float2*)(g_k3 + gh);
            a00 = ylo.x + (DT * 0.125f) * (k1l.x + 3.f * (k2l.x + k3l.x) + k00);
            a01 = ylo.y + (DT * 0.125f) * (k1l.y + 3.f * (k2l.y + k3l.y) + k01);
            a10 = yhi.x + (DT * 0.125f) * (k1h.x + 3.f * (k2h.x + k3h.x) + k10);
            a11 = yhi.y + (DT * 0.125f) * (k1h.y + 3.f * (k2h.y + k3h.y) + k11);
        }
        if (ST < 3) {
            *(float2*)(AR + ol) = make_float2(a00, a01);
            *(float2*)(AR + oh) = make_float2(a10, a11);
        } else {
            *(float2*)(Y + ol) = make_float2(a00, a01);
            *(float2*)(Y + oh) = make_float2(a10, a11);
        }
        sts1u(sbase + astb2(quad, cb), f2bf2(a00, a01));
        sts1u(sbase + astb2(quad + 8, cb), f2bf2(a10, a11));
    }
}

__global__ void __launch_bounds__(256, 1)
ode_mma_kernel(const int* __restrict__ lead, const int* __restrict__ nsp,
               const float* __restrict__ bl1, const float* __restrict__ bl2,
               const float* __restrict__ gn, const float* __restrict__ bn) {
    extern __shared__ __align__(16) float smF[];
    uint32_t sbase;
    asm("{ .reg .u64 t; cvta.to.shared.u64 t, %1; cvt.u32.u64 %0, t; }"
        : "=r"(sbase) : "l"((const void*)smF));
    int tid = threadIdx.x, warp = tid >> 5, lane = tid & 31;
    int r0 = blockIdx.x * 16;
    int steps = lead[r0 >> 8];
    int ns = nsp ? nsp[0] : 50;
    if (steps > ns) steps = ns;
    if (steps < 0) steps = 0;

    // load W1 resident (one cp.async group)
#pragma unroll
    for (int i = 0; i < 32; i++) {
        int off = (tid + i * 256) * 16;
        cp_async16(sbase + OFF_W1R + off, (const char*)g_wt1 + off);
    }
    cp_commit();

    float* CST = smF + OFF_CST / 4;
    for (int i = tid; i < 256; i += 256) {
        CST[i] = bl1[i]; CST[256 + i] = bl2[i];
        CST[512 + i] = gn[i]; CST[768 + i] = bn[i];
    }
    for (int idx = tid; idx < 16 * 128; idx += 256) {
        int r = idx >> 7, kp = idx & 127;
        int cb = kp * 2;
        float2 vv = *(const float2*)(g_x1 + (r0 + r) * 256 + cb);
        smF[OFF_YS / 4 + r * RMJ + cb] = vv.x;
        smF[OFF_YS / 4 + r * RMJ + cb + 1] = vv.y;
        sts1u(sbase + astb2(r, cb), f2bf2(vv.x, vv.y));
    }
    cp_wait0();
    __syncthreads();

    float acc[4][4];
    for (int s = 0; s < steps; s++) {
#pragma unroll 1
        for (int st = 0; st < 4; st++) {
            // prime W2 blocks 0,1 (overlaps with GEMM1)
            prefB(sbase + OFF_W20, g_wt2, tid);
            prefB(sbase + OFF_W21, g_wt2 + 4096, tid);
            run_gemm1(sbase, acc, warp, lane);
            __syncthreads();
            // epi1: h1 = relu(acc + bl1) -> A-stage (bf16)
            {
                int quad = lane >> 2, q = lane & 3;
#pragma unroll
                for (int t = 0; t < 4; t++) {
                    int cb = warp * 32 + t * 8 + q * 2;
                    float2 bias = *(float2*)(CST + cb);
                    sts1u(sbase + astb2(quad, cb),
                          f2bf2(fmaxf(acc[t][0] + bias.x, 0.f), fmaxf(acc[t][1] + bias.y, 0.f)));
                    sts1u(sbase + astb2(quad + 8, cb),
                          f2bf2(fmaxf(acc[t][2] + bias.x, 0.f), fmaxf(acc[t][3] + bias.y, 0.f)));
                }
            }
            // GEMM2's internal first wait+sync publishes epi1 stores
            run_gemm2(sbase, acc, warp, lane, tid);
            if (st == 0)      epi2<0>(smF, sbase, acc, warp, lane, tid, r0);
            else if (st == 1) epi2<1>(smF, sbase, acc, warp, lane, tid, r0);
            else if (st == 2) epi2<2>(smF, sbase, acc, warp, lane, tid, r0);
            else              epi2<3>(smF, sbase, acc, warp, lane, tid, r0);
            __syncthreads();
        }
    }
    cp_wait0();
    __syncthreads();
    for (int idx = tid; idx < 16 * 256; idx += 256) {
        int r = idx >> 8, c = idx & 255;
        g_ode[(r0 + r) * 256 + c] = smF[OFF_YS / 4 + r * RMJ + c];
    }
}

// ---------------------------------------------------------------------------
// K5: out = LN(x1 + ode; g2,b2)
// ---------------------------------------------------------------------------
__global__ void final_ln_kernel(const float* __restrict__ g2, const float* __restrict__ b2,
                                float* __restrict__ out) {
    int tid = threadIdx.x, lane = tid & 31, w = tid >> 5;
    int r = blockIdx.x * 8 + w;
    float v[8], ls = 0.f, lq = 0.f;
#pragma unroll
    for (int u = 0; u < 8; u++) {
        int c = lane + 32 * u;
        float t = g_x1[r * CDIM + c] + g_ode[r * CDIM + c];
        v[u] = t; ls += t; lq += t * t;
    }
#pragma unroll
    for (int o = 16; o > 0; o >>= 1) {
        ls += __shfl_xor_sync(0xffffffffu, ls, o);
        lq += __shfl_xor_sync(0xffffffffu, lq, o);
    }
    float mean = ls * (1.f / 256.f);
    float rstd = rsqrtf(lq * (1.f / 256.f) - mean * mean + EPSLN);
#pragma unroll
    for (int u = 0; u < 8; u++) {
        int c = lane + 32 * u;
        out[r * CDIM + c] = (v[u] - mean) * rstd * g2[c] + b2[c];
    }
}

// ---------------------------------------------------------------------------
// Launch
// ---------------------------------------------------------------------------
extern "C" void kernel_launch(void* const* d_in, const int* in_sizes, int n_in,
                              void* d_out, int out_size) {
    const float* x    = (const float*)d_in[0];
    const float* wqkv = (const float*)d_in[1];
    const float* bqkv = (const float*)d_in[2];
    const float* wo   = (const float*)d_in[3];
    const float* bo   = (const float*)d_in[4];
    const float* g1   = (const float*)d_in[5];
    const float* b1   = (const float*)d_in[6];
    const float* g2   = (const float*)d_in[7];
    const float* b2   = (const float*)d_in[8];
    const float* wl1  = (const float*)d_in[9];
    const float* bl1  = (const float*)d_in[10];
    const float* wl2  = (const float*)d_in[11];
    const float* bl2  = (const float*)d_in[12];
    const float* gn   = (const float*)d_in[13];
    const float* bn   = (const float*)d_in[14];
    const int* lead   = (const int*)d_in[15];
    const int* nsteps = (n_in > 16) ? (const int*)d_in[16] : nullptr;
    float* out = (float*)d_out;

    cudaFuncSetAttribute(attn_kernel, cudaFuncAttributeMaxDynamicSharedMemorySize, ATTN_SMEM);
    cudaFuncSetAttribute(ode_mma_kernel, cudaFuncAttributeMaxDynamicSharedMemorySize, ODE_SMEM);
    cudaFuncSetAttribute(qkv_mma_kernel, cudaFuncAttributeMaxDynamicSharedMemorySize, QKV_SMEM);
    cudaFuncSetAttribute(proj_mma_kernel, cudaFuncAttributeMaxDynamicSharedMemorySize, PROJ_SMEM);

    prep_w_kernel<<<128, 256>>>(wl1, wl2);
    prep_qkv_kernel<<<dim3(256, 3), 256>>>(wqkv);
    prep_wo_kernel<<<256, 256>>>(wo);
    qkv_mma_kernel<<<dim3(128, 3), 256, QKV_SMEM>>>(x, bqkv);
    attn_kernel<<<128, 256, ATTN_SMEM>>>();
    proj_mma_kernel<<<128, 256, PROJ_SMEM>>>(x, bo, g1, b1);
    ode_mma_kernel<<<128, 256, ODE_SMEM>>>(lead, nsteps, bl1, bl2, gn, bn);
    final_ln_kernel<<<256, 256>>>(g2, b2, out);
}